// round 2
// baseline (speedup 1.0000x reference)
#include <cuda_runtime.h>

#define Bk 64
#define Pk 12
#define Qk 12
#define Nk 1024
#define Dk 64

// ---------------- scratch (device globals; no allocations allowed) ----------------
__device__ float g_se[Nk * Dk];                       // spatial embedding  [N,D]
__device__ float g_te[Bk * Pk * Dk];                  // temporal embedding [B*P,D]
__device__ float g_Xe[(size_t)Bk * Pk * Nk * Dk];     // FC_in output       [B,P,N,D]
__device__ float g_seq1[(size_t)Bk * Pk * Nk * Dk];   // layer-1 sequence   [B,P,N,D]
__device__ float g_s1[Bk * Nk * Dk];                  // layer-1 state      [B,N,D]
__device__ float g_s2[Bk * Nk * Dk];                  // layer-2 state      [B,N,D]
// folded weights: support = I  =>  gconv weight = W[:2D] + W[2D:]
__device__ float g_Wx1[64 * 192];   // [k][0:128]=gate-x, [k][128:192]=cand-x
__device__ float g_Wsg1[64 * 128];  // gate-s
__device__ float g_Wsc1[64 * 64];   // cand-s
__device__ float g_Wx2[64 * 192];
__device__ float g_Wsg2[64 * 128];
__device__ float g_Wsc2[64 * 64];

// ---------------- weight folding ----------------
__global__ void k_prep(const float* __restrict__ Wg1, const float* __restrict__ Wc1,
                       const float* __restrict__ Wg2, const float* __restrict__ Wc2) {
    int tid = blockIdx.x * blockDim.x + threadIdx.x;
    int stride = gridDim.x * blockDim.x;
    for (int idx = tid; idx < 64 * 192; idx += stride) {
        int k = idx / 192, j = idx - k * 192;
        float a, b;
        if (j < 128) {
            a = Wg1[k * 128 + j] + Wg1[(128 + k) * 128 + j];
            b = Wg2[k * 128 + j] + Wg2[(128 + k) * 128 + j];
        } else {
            int j2 = j - 128;
            a = Wc1[k * 64 + j2] + Wc1[(128 + k) * 64 + j2];
            b = Wc2[k * 64 + j2] + Wc2[(128 + k) * 64 + j2];
        }
        g_Wx1[idx] = a; g_Wx2[idx] = b;
    }
    for (int idx = tid; idx < 64 * 128; idx += stride) {
        int k = idx >> 7, j = idx & 127;
        g_Wsg1[idx] = Wg1[(64 + k) * 128 + j] + Wg1[(192 + k) * 128 + j];
        g_Wsg2[idx] = Wg2[(64 + k) * 128 + j] + Wg2[(192 + k) * 128 + j];
    }
    for (int idx = tid; idx < 64 * 64; idx += stride) {
        int k = idx >> 6, j = idx & 63;
        g_Wsc1[idx] = Wc1[(64 + k) * 64 + j] + Wc1[(192 + k) * 64 + j];
        g_Wsc2[idx] = Wc2[(64 + k) * 64 + j] + Wc2[(192 + k) * 64 + j];
    }
}

// ---------------- spatial embedding: relu(SE@W1+b1)@W2+b2 ----------------
__global__ void k_se(const float* __restrict__ SE, const float* __restrict__ W1,
                     const float* __restrict__ b1, const float* __restrict__ W2,
                     const float* __restrict__ b2) {
    __shared__ float xs[64], hs[64];
    int n = blockIdx.x, d = threadIdx.x;
    xs[d] = SE[n * 64 + d];
    __syncthreads();
    float a = b1[d];
#pragma unroll 8
    for (int k = 0; k < 64; k++) a = fmaf(xs[k], W1[k * 64 + d], a);
    hs[d] = fmaxf(a, 0.f);
    __syncthreads();
    float o = b2[d];
#pragma unroll 8
    for (int k = 0; k < 64; k++) o = fmaf(hs[k], W2[k * 64 + d], o);
    g_se[n * 64 + d] = o;
}

// ---------------- temporal embedding (one-hot @ W = row gather) ----------------
__global__ void k_te(const int* __restrict__ TE, const float* __restrict__ W1,
                     const float* __restrict__ b1, const float* __restrict__ W2,
                     const float* __restrict__ b2) {
    __shared__ float hs[64];
    int row = blockIdx.x;              // b*P + p, p < P
    int b = row / Pk, p = row - b * Pk;
    int d = threadIdx.x;
    int base = (b * (Pk + Qk) + p) * 2;
    int t0 = TE[base], t1 = TE[base + 1];
    float a = W1[t0 * 64 + d] + W1[(7 + t1) * 64 + d] + b1[d];
    hs[d] = fmaxf(a, 0.f);
    __syncthreads();
    float o = b2[d];
#pragma unroll 8
    for (int k = 0; k < 64; k++) o = fmaf(hs[k], W2[k * 64 + d], o);
    g_te[row * 64 + d] = o;
}

// ---------------- FC_in: Xe = relu(x*W1+b1)@W2 + b2 + se + te ----------------
__global__ __launch_bounds__(256) void k_fc_in(const float* __restrict__ X,
    const float* __restrict__ W1, const float* __restrict__ b1,
    const float* __restrict__ W2, const float* __restrict__ b2) {
    __shared__ float sW2[64 * 64];
    __shared__ float sH[64 * 64];
    __shared__ float sx[64];
    __shared__ float sw1[64], sb1[64], sb2[64];
    int tid = threadIdx.x;
    for (int i = tid; i < 4096; i += 256) sW2[i] = W2[i];
    if (tid < 64) { sw1[tid] = W1[tid]; sb1[tid] = b1[tid]; sb2[tid] = b2[tid]; }
    int row0 = blockIdx.x * 64;
    if (tid >= 64 && tid < 128) sx[tid - 64] = X[row0 + tid - 64];
    __syncthreads();
    for (int idx = tid; idx < 4096; idx += 256) {
        int i = idx >> 6, d = idx & 63;
        sH[idx] = fmaxf(fmaf(sx[i], sw1[d], sb1[d]), 0.f);
    }
    __syncthreads();
    int lane = tid & 31, w = tid >> 5, c0 = lane * 2;
    float acc[8][2];
#pragma unroll
    for (int ri = 0; ri < 8; ri++) { acc[ri][0] = 0.f; acc[ri][1] = 0.f; }
#pragma unroll 8
    for (int k = 0; k < 64; k++) {
        float2 wv = *(const float2*)&sW2[k * 64 + c0];
#pragma unroll
        for (int ri = 0; ri < 8; ri++) {
            float h = sH[(w + ri * 8) * 64 + k];
            acc[ri][0] = fmaf(h, wv.x, acc[ri][0]);
            acc[ri][1] = fmaf(h, wv.y, acc[ri][1]);
        }
    }
#pragma unroll
    for (int ri = 0; ri < 8; ri++) {
        int i = w + ri * 8; int r = row0 + i;
        int n = r & (Nk - 1); int bp = r >> 10;
        float o0 = acc[ri][0] + sb2[c0]     + g_se[n * 64 + c0]     + g_te[bp * 64 + c0];
        float o1 = acc[ri][1] + sb2[c0 + 1] + g_se[n * 64 + c0 + 1] + g_te[bp * 64 + c0 + 1];
        g_Xe[(size_t)r * 64 + c0]     = o0;
        g_Xe[(size_t)r * 64 + c0 + 1] = o1;
    }
}

// ---------------- zero states ----------------
__global__ void k_zero() {
    int i = blockIdx.x * blockDim.x + threadIdx.x;
    g_s1[i] = 0.f; g_s2[i] = 0.f;
}

// ---------------- fused DCGRU step (row-local; support = I) ----------------
// dynamic smem layout (floats):
//  sWx[12288] sWsg[8192] sWsc[4096] sX[4096] sS[4096] sRU[8192] sbg[128] sbc[64]
__global__ __launch_bounds__(256) void k_step(int layer, int t,
        const float* __restrict__ bg, const float* __restrict__ bc) {
    extern __shared__ float sm[];
    float* sWx  = sm;
    float* sWsg = sm + 12288;
    float* sWsc = sm + 20480;
    float* sX   = sm + 24576;
    float* sS   = sm + 28672;
    float* sRU  = sm + 32768;
    float* sbg  = sm + 40960;
    float* sbc  = sm + 41088;

    const float* Xbase = (layer == 0) ? g_Xe : g_seq1;
    float* S           = (layer == 0) ? g_s1 : g_s2;
    float* SeqOut      = (layer == 0) ? g_seq1 : (float*)0;
    const float* Wx    = (layer == 0) ? g_Wx1  : g_Wx2;
    const float* Wsg   = (layer == 0) ? g_Wsg1 : g_Wsg2;
    const float* Wsc   = (layer == 0) ? g_Wsc1 : g_Wsc2;

    int tid = threadIdx.x;
    for (int i = tid; i < 12288; i += 256) sWx[i]  = Wx[i];
    for (int i = tid; i < 8192;  i += 256) sWsg[i] = Wsg[i];
    for (int i = tid; i < 4096;  i += 256) sWsc[i] = Wsc[i];
    if (tid < 128) sbg[tid] = bg[tid];
    if (tid < 64)  sbc[tid] = bc[tid];

    int row0 = blockIdx.x * 64;
    for (int i4 = tid; i4 < 1024; i4 += 256) {
        int i = i4 >> 4; int c = (i4 & 15) << 2;
        int r = row0 + i; int b = r >> 10; int n = r & 1023;
        *(float4*)&sX[i * 64 + c] =
            *(const float4*)&Xbase[((size_t)(b * Pk + t) * Nk + n) * 64 + c];
        *(float4*)&sS[i * 64 + c] = *(const float4*)&S[(size_t)r * 64 + c];
    }
    __syncthreads();

    int lane = tid & 31, w = tid >> 5;

    // ---- phase A: ru = sigmoid(x@Wxg + s@Wsg + bg), 128 cols ----
    {
        int c0 = lane << 2;
        float acc[8][4];
#pragma unroll
        for (int ri = 0; ri < 8; ri++)
#pragma unroll
            for (int c = 0; c < 4; c++) acc[ri][c] = 0.f;
#pragma unroll 4
        for (int k = 0; k < 64; k++) {
            float4 wg = *(const float4*)&sWx[k * 192 + c0];
            float4 ws = *(const float4*)&sWsg[k * 128 + c0];
#pragma unroll
            for (int ri = 0; ri < 8; ri++) {
                float x = sX[(w + ri * 8) * 64 + k];
                float s = sS[(w + ri * 8) * 64 + k];
                acc[ri][0] = fmaf(x, wg.x, acc[ri][0]); acc[ri][0] = fmaf(s, ws.x, acc[ri][0]);
                acc[ri][1] = fmaf(x, wg.y, acc[ri][1]); acc[ri][1] = fmaf(s, ws.y, acc[ri][1]);
                acc[ri][2] = fmaf(x, wg.z, acc[ri][2]); acc[ri][2] = fmaf(s, ws.z, acc[ri][2]);
                acc[ri][3] = fmaf(x, wg.w, acc[ri][3]); acc[ri][3] = fmaf(s, ws.w, acc[ri][3]);
            }
        }
#pragma unroll
        for (int ri = 0; ri < 8; ri++) {
            int i = w + ri * 8;
            float4 o;
            o.x = 1.f / (1.f + expf(-(acc[ri][0] + sbg[c0])));
            o.y = 1.f / (1.f + expf(-(acc[ri][1] + sbg[c0 + 1])));
            o.z = 1.f / (1.f + expf(-(acc[ri][2] + sbg[c0 + 2])));
            o.w = 1.f / (1.f + expf(-(acc[ri][3] + sbg[c0 + 3])));
            *(float4*)&sRU[i * 128 + c0] = o;
        }
    }
    __syncthreads();

    // ---- r <- r * s (in place, keep u at cols 64..127) ----
    for (int idx = tid; idx < 4096; idx += 256) {
        int i = idx >> 6, k = idx & 63;
        sRU[i * 128 + k] *= sS[i * 64 + k];
    }
    __syncthreads();

    // ---- phase B: c = tanh(x@Wxc + (r*s)@Wsc + bc); new = u*s + (1-u)*c ----
    {
        int c0 = lane << 1;
        float acc[8][2];
#pragma unroll
        for (int ri = 0; ri < 8; ri++) { acc[ri][0] = 0.f; acc[ri][1] = 0.f; }
#pragma unroll 4
        for (int k = 0; k < 64; k++) {
            float2 wxv = *(const float2*)&sWx[k * 192 + 128 + c0];
            float2 wcv = *(const float2*)&sWsc[k * 64 + c0];
#pragma unroll
            for (int ri = 0; ri < 8; ri++) {
                float x  = sX[(w + ri * 8) * 64 + k];
                float rs = sRU[(w + ri * 8) * 128 + k];
                acc[ri][0] = fmaf(x, wxv.x, acc[ri][0]); acc[ri][0] = fmaf(rs, wcv.x, acc[ri][0]);
                acc[ri][1] = fmaf(x, wxv.y, acc[ri][1]); acc[ri][1] = fmaf(rs, wcv.y, acc[ri][1]);
            }
        }
#pragma unroll
        for (int ri = 0; ri < 8; ri++) {
            int i = w + ri * 8; int r = row0 + i;
            int b = r >> 10, n = r & 1023;
#pragma unroll
            for (int c = 0; c < 2; c++) {
                int j = c0 + c;
                float cc = tanhf(acc[ri][c] + sbc[j]);
                float u  = sRU[i * 128 + 64 + j];
                float sv = sS[i * 64 + j];
                float nv = fmaf(u, sv - cc, cc);   // u*s + (1-u)*c
                S[(size_t)r * 64 + j] = nv;
                if (SeqOut) SeqOut[((size_t)(b * Pk + t) * Nk + n) * 64 + j] = nv;
            }
        }
    }
}

// ---------------- FC_out: y = relu(h@Wo1+bo1)@Wo2+bo2; out[b,q,n] ----------------
__global__ __launch_bounds__(256) void k_fc_out(
        const float* __restrict__ W1, const float* __restrict__ b1,
        const float* __restrict__ W2, const float* __restrict__ b2,
        float* __restrict__ out) {
    __shared__ float sW1[64 * 64];
    __shared__ float sHin[64 * 64];
    __shared__ float sH[64 * 65];
    __shared__ float sW2[64 * 12];
    __shared__ float sb1v[64], sb2v[12];
    int tid = threadIdx.x;
    for (int i = tid; i < 4096; i += 256) sW1[i] = W1[i];
    for (int i = tid; i < 768; i += 256) sW2[i] = W2[i];
    if (tid < 64) sb1v[tid] = b1[tid];
    if (tid < 12) sb2v[tid] = b2[tid];
    int row0 = blockIdx.x * 64;
    for (int i4 = tid; i4 < 1024; i4 += 256) {
        int i = i4 >> 4, c = (i4 & 15) << 2;
        *(float4*)&sHin[i * 64 + c] = *(const float4*)&g_s2[(size_t)(row0 + i) * 64 + c];
    }
    __syncthreads();
    int lane = tid & 31, w = tid >> 5, c0 = lane * 2;
    float acc[8][2];
#pragma unroll
    for (int ri = 0; ri < 8; ri++) { acc[ri][0] = 0.f; acc[ri][1] = 0.f; }
#pragma unroll 8
    for (int k = 0; k < 64; k++) {
        float2 wv = *(const float2*)&sW1[k * 64 + c0];
#pragma unroll
        for (int ri = 0; ri < 8; ri++) {
            float h = sHin[(w + ri * 8) * 64 + k];
            acc[ri][0] = fmaf(h, wv.x, acc[ri][0]);
            acc[ri][1] = fmaf(h, wv.y, acc[ri][1]);
        }
    }
#pragma unroll
    for (int ri = 0; ri < 8; ri++) {
        int i = w + ri * 8;
        sH[i * 65 + c0]     = fmaxf(acc[ri][0] + sb1v[c0], 0.f);
        sH[i * 65 + c0 + 1] = fmaxf(acc[ri][1] + sb1v[c0 + 1], 0.f);
    }
    __syncthreads();
    int i = tid >> 2; int q0 = (tid & 3) * 3;
    float a0 = sb2v[q0], a1 = sb2v[q0 + 1], a2 = sb2v[q0 + 2];
#pragma unroll 8
    for (int k = 0; k < 64; k++) {
        float h = sH[i * 65 + k];
        a0 = fmaf(h, sW2[k * 12 + q0],     a0);
        a1 = fmaf(h, sW2[k * 12 + q0 + 1], a1);
        a2 = fmaf(h, sW2[k * 12 + q0 + 2], a2);
    }
    int r = row0 + i, b = r >> 10, n = r & 1023;
    out[(((size_t)b * Qk + q0)     << 10) + n] = a0;
    out[(((size_t)b * Qk + q0 + 1) << 10) + n] = a1;
    out[(((size_t)b * Qk + q0 + 2) << 10) + n] = a2;
}

// ---------------- launch ----------------
extern "C" void kernel_launch(void* const* d_in, const int* in_sizes, int n_in,
                              void* d_out, int out_size) {
    const float* X     = (const float*)d_in[0];
    const float* SE    = (const float*)d_in[3];
    const float* W_se1 = (const float*)d_in[4];  const float* b_se1 = (const float*)d_in[5];
    const float* W_se2 = (const float*)d_in[6];  const float* b_se2 = (const float*)d_in[7];
    const float* W_te1 = (const float*)d_in[8];  const float* b_te1 = (const float*)d_in[9];
    const float* W_te2 = (const float*)d_in[10]; const float* b_te2 = (const float*)d_in[11];
    const float* W_in1 = (const float*)d_in[12]; const float* b_in1 = (const float*)d_in[13];
    const float* W_in2 = (const float*)d_in[14]; const float* b_in2 = (const float*)d_in[15];
    const float* Wg1   = (const float*)d_in[16]; const float* bg1   = (const float*)d_in[17];
    const float* Wc1   = (const float*)d_in[18]; const float* bc1   = (const float*)d_in[19];
    const float* Wg2   = (const float*)d_in[20]; const float* bg2   = (const float*)d_in[21];
    const float* Wc2   = (const float*)d_in[22]; const float* bc2   = (const float*)d_in[23];
    const float* W_o1  = (const float*)d_in[24]; const float* b_o1  = (const float*)d_in[25];
    const float* W_o2  = (const float*)d_in[26]; const float* b_o2  = (const float*)d_in[27];
    const int*   TE    = (const int*)d_in[28];
    float* out = (float*)d_out;

    const size_t step_smem = (size_t)41152 * 4;   // 164,608 B dynamic smem
    cudaFuncSetAttribute(k_step, cudaFuncAttributeMaxDynamicSharedMemorySize,
                         (int)step_smem);

    k_prep<<<48, 256>>>(Wg1, Wc1, Wg2, Wc2);
    k_se<<<Nk, 64>>>(SE, W_se1, b_se1, W_se2, b_se2);
    k_te<<<Bk * Pk, 64>>>(TE, W_te1, b_te1, W_te2, b_te2);
    k_fc_in<<<Bk * Pk * Nk / 64, 256>>>(X, W_in1, b_in1, W_in2, b_in2);
    k_zero<<<Bk * Nk * Dk / 256, 256>>>();

    for (int t = 0; t < Pk; t++)
        k_step<<<Bk * Nk / 64, 256, step_smem>>>(0, t, bg1, bc1);
    for (int t = 0; t < Pk; t++)
        k_step<<<Bk * Nk / 64, 256, step_smem>>>(1, t, bg2, bc2);

    k_fc_out<<<Bk * Nk / 64, 256>>>(W_o1, b_o1, W_o2, b_o2, out);
}

// round 3
// speedup vs baseline: 1.9014x; 1.9014x over previous
#include <cuda_runtime.h>

#define Bk 64
#define Pk 12
#define Qk 12
#define Nk 1024
#define Dk 64

typedef unsigned long long ull;

__device__ __forceinline__ ull ffma2(ull a, ull b, ull c) {
    ull d;
    asm("fma.rn.f32x2 %0, %1, %2, %3;" : "=l"(d) : "l"(a), "l"(b), "l"(c));
    return d;
}
__device__ __forceinline__ float2 u2f(ull a) {
    float2 f;
    asm("mov.b64 {%0, %1}, %2;" : "=f"(f.x), "=f"(f.y) : "l"(a));
    return f;
}
__device__ __forceinline__ float sigm(float z) {
    z = fminf(fmaxf(z, -30.f), 30.f);
    return __fdividef(1.f, 1.f + __expf(-z));
}
__device__ __forceinline__ float tanh_fast(float z) {
    z = fminf(fmaxf(z, -15.f), 15.f);
    float e = __expf(-2.f * z);
    return __fdividef(1.f - e, 1.f + e);
}

// ---------------- scratch (device globals; no allocations allowed) ----------------
__device__ float g_se[Nk * Dk];                       // spatial embedding  [N,D]
__device__ float g_te[Bk * Pk * Dk];                  // temporal embedding [B*P,D]
__device__ float g_Xe[(size_t)Bk * Pk * Nk * Dk];     // FC_in output       [B,P,N,D]
__device__ float g_seq1[(size_t)Bk * Pk * Nk * Dk];   // layer-1 sequence   [B,P,N,D]
__device__ float g_s2[Bk * Nk * Dk];                  // layer-2 final state[B,N,D]

// folded (support = I) weights, packed for f32x2:
// element at ((k>>1)*COLS + c)*2 + (k&1) = W[k][c], i.e. float2 holds (W[2k2][c], W[2k2+1][c])
__device__ float g_Wgx[2][64 * 128];   // gate, x-part     [k][128]
__device__ float g_Wgs[2][64 * 128];   // gate, s-part     [k][128]
__device__ float g_Wcx[2][64 * 64];    // candidate x-part [k][64]
__device__ float g_Wcs[2][64 * 64];    // candidate s-part [k][64]

// ---------------- weight folding + packing ----------------
__global__ void k_prep(const float* __restrict__ Wg1, const float* __restrict__ Wc1,
                       const float* __restrict__ Wg2, const float* __restrict__ Wc2) {
    int tid = blockIdx.x * blockDim.x + threadIdx.x;
    int stride = gridDim.x * blockDim.x;
    for (int idx = tid; idx < 64 * 128; idx += stride) {
        int k = idx >> 7, c = idx & 127;
        int d = ((k >> 1) * 128 + c) * 2 + (k & 1);
        g_Wgx[0][d] = Wg1[k * 128 + c] + Wg1[(128 + k) * 128 + c];
        g_Wgx[1][d] = Wg2[k * 128 + c] + Wg2[(128 + k) * 128 + c];
        g_Wgs[0][d] = Wg1[(64 + k) * 128 + c] + Wg1[(192 + k) * 128 + c];
        g_Wgs[1][d] = Wg2[(64 + k) * 128 + c] + Wg2[(192 + k) * 128 + c];
    }
    for (int idx = tid; idx < 64 * 64; idx += stride) {
        int k = idx >> 6, c = idx & 63;
        int d = ((k >> 1) * 64 + c) * 2 + (k & 1);
        g_Wcx[0][d] = Wc1[k * 64 + c] + Wc1[(128 + k) * 64 + c];
        g_Wcx[1][d] = Wc2[k * 64 + c] + Wc2[(128 + k) * 64 + c];
        g_Wcs[0][d] = Wc1[(64 + k) * 64 + c] + Wc1[(192 + k) * 64 + c];
        g_Wcs[1][d] = Wc2[(64 + k) * 64 + c] + Wc2[(192 + k) * 64 + c];
    }
}

// ---------------- spatial embedding: relu(SE@W1+b1)@W2+b2 ----------------
__global__ void k_se(const float* __restrict__ SE, const float* __restrict__ W1,
                     const float* __restrict__ b1, const float* __restrict__ W2,
                     const float* __restrict__ b2) {
    __shared__ float xs[64], hs[64];
    int n = blockIdx.x, d = threadIdx.x;
    xs[d] = SE[n * 64 + d];
    __syncthreads();
    float a = b1[d];
#pragma unroll 8
    for (int k = 0; k < 64; k++) a = fmaf(xs[k], W1[k * 64 + d], a);
    hs[d] = fmaxf(a, 0.f);
    __syncthreads();
    float o = b2[d];
#pragma unroll 8
    for (int k = 0; k < 64; k++) o = fmaf(hs[k], W2[k * 64 + d], o);
    g_se[n * 64 + d] = o;
}

// ---------------- temporal embedding (one-hot @ W = row gather) ----------------
__global__ void k_te(const int* __restrict__ TE, const float* __restrict__ W1,
                     const float* __restrict__ b1, const float* __restrict__ W2,
                     const float* __restrict__ b2) {
    __shared__ float hs[64];
    int row = blockIdx.x;              // b*P + p
    int b = row / Pk, p = row - b * Pk;
    int d = threadIdx.x;
    int base = (b * (Pk + Qk) + p) * 2;
    int t0 = TE[base], t1 = TE[base + 1];
    float a = W1[t0 * 64 + d] + W1[(7 + t1) * 64 + d] + b1[d];
    hs[d] = fmaxf(a, 0.f);
    __syncthreads();
    float o = b2[d];
#pragma unroll 8
    for (int k = 0; k < 64; k++) o = fmaf(hs[k], W2[k * 64 + d], o);
    g_te[row * 64 + d] = o;
}

// ---------------- FC_in: Xe = relu(x*W1+b1)@W2 + b2 + se + te (f32x2) ----------------
__global__ __launch_bounds__(256) void k_fc_in(const float* __restrict__ X,
    const float* __restrict__ W1, const float* __restrict__ b1,
    const float* __restrict__ W2, const float* __restrict__ b2) {
    __shared__ float sW2p[64 * 64];    // packed: ((k>>1)*64+c)*2 + (k&1)
    __shared__ float sH[64 * 64];
    __shared__ float sx[64];
    __shared__ float sw1[64], sb1[64], sb2[64];
    int tid = threadIdx.x;
    for (int i = tid; i < 4096; i += 256) {
        int k = i >> 6, c = i & 63;
        sW2p[((k >> 1) * 64 + c) * 2 + (k & 1)] = W2[i];
    }
    if (tid < 64) { sw1[tid] = W1[tid]; sb1[tid] = b1[tid]; sb2[tid] = b2[tid]; }
    int row0 = blockIdx.x * 64;
    if (tid >= 64 && tid < 128) sx[tid - 64] = X[row0 + tid - 64];
    __syncthreads();
    for (int idx = tid; idx < 4096; idx += 256) {
        int i = idx >> 6, d = idx & 63;
        sH[idx] = fmaxf(fmaf(sx[i], sw1[d], sb1[d]), 0.f);
    }
    __syncthreads();
    int lane = tid & 31, w = tid >> 5, c0 = lane * 2;
    const ull* W2p = (const ull*)sW2p;
    ull acc[8][2];
#pragma unroll
    for (int ri = 0; ri < 8; ri++) { acc[ri][0] = 0ULL; acc[ri][1] = 0ULL; }
#pragma unroll 4
    for (int k2 = 0; k2 < 32; k2++) {
        ulonglong2 wv = *(const ulonglong2*)&W2p[k2 * 64 + c0];
#pragma unroll
        for (int ri = 0; ri < 8; ri++) {
            ull hv = *(const ull*)&sH[(w + ri * 8) * 64 + 2 * k2];
            acc[ri][0] = ffma2(hv, wv.x, acc[ri][0]);
            acc[ri][1] = ffma2(hv, wv.y, acc[ri][1]);
        }
    }
#pragma unroll
    for (int ri = 0; ri < 8; ri++) {
        int i = w + ri * 8; int r = row0 + i;
        int n = r & (Nk - 1); int bp = r >> 10;
        float2 p0 = u2f(acc[ri][0]), p1 = u2f(acc[ri][1]);
        float o0 = p0.x + p0.y + sb2[c0]     + g_se[n * 64 + c0]     + g_te[bp * 64 + c0];
        float o1 = p1.x + p1.y + sb2[c0 + 1] + g_se[n * 64 + c0 + 1] + g_te[bp * 64 + c0 + 1];
        *(float2*)&g_Xe[(size_t)r * 64 + c0] = make_float2(o0, o1);
    }
}

// ---------------- persistent DCGRU layer: all 12 steps in one kernel ----------------
// smem (floats): sWgx[8192] sWgs[8192] sWcx[4096] sWcs[4096] sX[4096] sS[4096] sR[4096] sbg[128] sbc[64]
__global__ __launch_bounds__(256, 1) void k_layer(int layer,
        const float* __restrict__ bg, const float* __restrict__ bc) {
    extern __shared__ float sm[];
    float* sWgx = sm;
    float* sWgs = sm + 8192;
    float* sWcx = sm + 16384;
    float* sWcs = sm + 20480;
    float* sX   = sm + 24576;
    float* sS   = sm + 28672;
    float* sR   = sm + 32768;
    float* sbg  = sm + 36864;
    float* sbc  = sm + 36992;

    int tid = threadIdx.x;
    {
        const float4* a = (const float4*)g_Wgx[layer];
        const float4* b = (const float4*)g_Wgs[layer];
        float4* da = (float4*)sWgx; float4* db = (float4*)sWgs;
        for (int i = tid; i < 2048; i += 256) { da[i] = a[i]; db[i] = b[i]; }
        const float4* c = (const float4*)g_Wcx[layer];
        const float4* d = (const float4*)g_Wcs[layer];
        float4* dc = (float4*)sWcx; float4* dd = (float4*)sWcs;
        for (int i = tid; i < 1024; i += 256) { dc[i] = c[i]; dd[i] = d[i]; }
    }
    if (tid < 128) sbg[tid] = bg[tid];
    if (tid < 64)  sbc[tid] = bc[tid];
    for (int i = tid; i < 4096; i += 256) sS[i] = 0.f;

    int row0 = blockIdx.x * 64;
    int b = row0 >> 10; int n0 = row0 & 1023;
    const float* Xbase = (layer == 0) ? g_Xe : g_seq1;
    {
        const float4* x0 = (const float4*)&Xbase[((size_t)(b * Pk) * Nk + n0) * 64];
        float4* d = (float4*)sX;
#pragma unroll
        for (int q = 0; q < 4; q++) d[tid + q * 256] = x0[tid + q * 256];
    }
    __syncthreads();

    int lane = tid & 31, w = tid >> 5, j0 = lane * 2;
    const ull* Wgx2 = (const ull*)sWgx;
    const ull* Wgs2 = (const ull*)sWgs;
    const ull* Wcx2 = (const ull*)sWcx;
    const ull* Wcs2 = (const ull*)sWcs;
    float4 pre[4];

    for (int t = 0; t < Pk; t++) {
        // prefetch next x tile (overlaps phase-A compute)
        if (t + 1 < Pk) {
            const float4* xs = (const float4*)&Xbase[((size_t)(b * Pk + t + 1) * Nk + n0) * 64];
#pragma unroll
            for (int q = 0; q < 4; q++) pre[q] = xs[tid + q * 256];
        }

        // ---- phase A: gates (128 cols: r at j0, u at 64+j0) ----
        ull accA[8][4];
#pragma unroll
        for (int ri = 0; ri < 8; ri++) {
            accA[ri][0] = 0ULL; accA[ri][1] = 0ULL; accA[ri][2] = 0ULL; accA[ri][3] = 0ULL;
        }
#pragma unroll 2
        for (int kk = 0; kk < 16; kk++) {
            ulonglong2 wrx0 = *(const ulonglong2*)&Wgx2[(2 * kk) * 128 + j0];
            ulonglong2 wux0 = *(const ulonglong2*)&Wgx2[(2 * kk) * 128 + 64 + j0];
            ulonglong2 wrs0 = *(const ulonglong2*)&Wgs2[(2 * kk) * 128 + j0];
            ulonglong2 wus0 = *(const ulonglong2*)&Wgs2[(2 * kk) * 128 + 64 + j0];
            ulonglong2 wrx1 = *(const ulonglong2*)&Wgx2[(2 * kk + 1) * 128 + j0];
            ulonglong2 wux1 = *(const ulonglong2*)&Wgx2[(2 * kk + 1) * 128 + 64 + j0];
            ulonglong2 wrs1 = *(const ulonglong2*)&Wgs2[(2 * kk + 1) * 128 + j0];
            ulonglong2 wus1 = *(const ulonglong2*)&Wgs2[(2 * kk + 1) * 128 + 64 + j0];
#pragma unroll
            for (int ri = 0; ri < 8; ri++) {
                int i = w + ri * 8;
                ulonglong2 xv = *(const ulonglong2*)&sX[i * 64 + 4 * kk];
                ulonglong2 sv = *(const ulonglong2*)&sS[i * 64 + 4 * kk];
                accA[ri][0] = ffma2(xv.x, wrx0.x, accA[ri][0]);
                accA[ri][1] = ffma2(xv.x, wrx0.y, accA[ri][1]);
                accA[ri][2] = ffma2(xv.x, wux0.x, accA[ri][2]);
                accA[ri][3] = ffma2(xv.x, wux0.y, accA[ri][3]);
                accA[ri][0] = ffma2(sv.x, wrs0.x, accA[ri][0]);
                accA[ri][1] = ffma2(sv.x, wrs0.y, accA[ri][1]);
                accA[ri][2] = ffma2(sv.x, wus0.x, accA[ri][2]);
                accA[ri][3] = ffma2(sv.x, wus0.y, accA[ri][3]);
                accA[ri][0] = ffma2(xv.y, wrx1.x, accA[ri][0]);
                accA[ri][1] = ffma2(xv.y, wrx1.y, accA[ri][1]);
                accA[ri][2] = ffma2(xv.y, wux1.x, accA[ri][2]);
                accA[ri][3] = ffma2(xv.y, wux1.y, accA[ri][3]);
                accA[ri][0] = ffma2(sv.y, wrs1.x, accA[ri][0]);
                accA[ri][1] = ffma2(sv.y, wrs1.y, accA[ri][1]);
                accA[ri][2] = ffma2(sv.y, wus1.x, accA[ri][2]);
                accA[ri][3] = ffma2(sv.y, wus1.y, accA[ri][3]);
            }
        }
        float ur[8][2];
#pragma unroll
        for (int ri = 0; ri < 8; ri++) {
            int i = w + ri * 8;
            float2 p0 = u2f(accA[ri][0]), p1 = u2f(accA[ri][1]);
            float r0 = sigm(p0.x + p0.y + sbg[j0]);
            float r1 = sigm(p1.x + p1.y + sbg[j0 + 1]);
            float2 p2 = u2f(accA[ri][2]), p3 = u2f(accA[ri][3]);
            ur[ri][0] = sigm(p2.x + p2.y + sbg[64 + j0]);
            ur[ri][1] = sigm(p3.x + p3.y + sbg[64 + j0 + 1]);
            float2 sv = *(const float2*)&sS[i * 64 + j0];
            *(float2*)&sR[i * 64 + j0] = make_float2(r0 * sv.x, r1 * sv.y);
        }
        __syncthreads();

        // ---- phase B: candidate (64 cols) ----
        ull accB[8][2];
#pragma unroll
        for (int ri = 0; ri < 8; ri++) { accB[ri][0] = 0ULL; accB[ri][1] = 0ULL; }
#pragma unroll 2
        for (int kk = 0; kk < 16; kk++) {
            ulonglong2 wx0 = *(const ulonglong2*)&Wcx2[(2 * kk) * 64 + j0];
            ulonglong2 wc0 = *(const ulonglong2*)&Wcs2[(2 * kk) * 64 + j0];
            ulonglong2 wx1 = *(const ulonglong2*)&Wcx2[(2 * kk + 1) * 64 + j0];
            ulonglong2 wc1 = *(const ulonglong2*)&Wcs2[(2 * kk + 1) * 64 + j0];
#pragma unroll
            for (int ri = 0; ri < 8; ri++) {
                int i = w + ri * 8;
                ulonglong2 xv = *(const ulonglong2*)&sX[i * 64 + 4 * kk];
                ulonglong2 rv = *(const ulonglong2*)&sR[i * 64 + 4 * kk];
                accB[ri][0] = ffma2(xv.x, wx0.x, accB[ri][0]);
                accB[ri][1] = ffma2(xv.x, wx0.y, accB[ri][1]);
                accB[ri][0] = ffma2(rv.x, wc0.x, accB[ri][0]);
                accB[ri][1] = ffma2(rv.x, wc0.y, accB[ri][1]);
                accB[ri][0] = ffma2(xv.y, wx1.x, accB[ri][0]);
                accB[ri][1] = ffma2(xv.y, wx1.y, accB[ri][1]);
                accB[ri][0] = ffma2(rv.y, wc1.x, accB[ri][0]);
                accB[ri][1] = ffma2(rv.y, wc1.y, accB[ri][1]);
            }
        }
        __syncthreads();   // all warps done reading sX/sR

        // install prefetched x(t+1)
        if (t + 1 < Pk) {
            float4* d = (float4*)sX;
#pragma unroll
            for (int q = 0; q < 4; q++) d[tid + q * 256] = pre[q];
        }

        // ---- epilogue: c = tanh(...), new = u*s + (1-u)*c ----
        float* out = (layer == 0)
            ? &g_seq1[((size_t)(b * Pk + t) * Nk + n0) * 64] : (float*)0;
#pragma unroll
        for (int ri = 0; ri < 8; ri++) {
            int i = w + ri * 8;
            float2 pc0 = u2f(accB[ri][0]), pc1 = u2f(accB[ri][1]);
            float c0v = tanh_fast(pc0.x + pc0.y + sbc[j0]);
            float c1v = tanh_fast(pc1.x + pc1.y + sbc[j0 + 1]);
            float2 sv = *(const float2*)&sS[i * 64 + j0];
            float nv0 = fmaf(ur[ri][0], sv.x - c0v, c0v);
            float nv1 = fmaf(ur[ri][1], sv.y - c1v, c1v);
            *(float2*)&sS[i * 64 + j0] = make_float2(nv0, nv1);
            if (out) *(float2*)&out[i * 64 + j0] = make_float2(nv0, nv1);
        }
        __syncthreads();
    }

    if (layer == 1) {
        float4* d = (float4*)&g_s2[(size_t)row0 * 64];
        const float4* s = (const float4*)sS;
#pragma unroll
        for (int q = 0; q < 4; q++) d[tid + q * 256] = s[tid + q * 256];
    }
}

// ---------------- FC_out: y = relu(h@Wo1+bo1)@Wo2+bo2; out[b,q,n] ----------------
__global__ __launch_bounds__(256) void k_fc_out(
        const float* __restrict__ W1, const float* __restrict__ b1,
        const float* __restrict__ W2, const float* __restrict__ b2,
        float* __restrict__ out) {
    __shared__ float sW1[64 * 64];
    __shared__ float sHin[64 * 64];
    __shared__ float sH[64 * 65];
    __shared__ float sW2[64 * 12];
    __shared__ float sb1v[64], sb2v[12];
    int tid = threadIdx.x;
    for (int i = tid; i < 4096; i += 256) sW1[i] = W1[i];
    for (int i = tid; i < 768; i += 256) sW2[i] = W2[i];
    if (tid < 64) sb1v[tid] = b1[tid];
    if (tid < 12) sb2v[tid] = b2[tid];
    int row0 = blockIdx.x * 64;
    for (int i4 = tid; i4 < 1024; i4 += 256) {
        int i = i4 >> 4, c = (i4 & 15) << 2;
        *(float4*)&sHin[i * 64 + c] = *(const float4*)&g_s2[(size_t)(row0 + i) * 64 + c];
    }
    __syncthreads();
    int lane = tid & 31, w = tid >> 5, c0 = lane * 2;
    float acc[8][2];
#pragma unroll
    for (int ri = 0; ri < 8; ri++) { acc[ri][0] = 0.f; acc[ri][1] = 0.f; }
#pragma unroll 8
    for (int k = 0; k < 64; k++) {
        float2 wv = *(const float2*)&sW1[k * 64 + c0];
#pragma unroll
        for (int ri = 0; ri < 8; ri++) {
            float h = sHin[(w + ri * 8) * 64 + k];
            acc[ri][0] = fmaf(h, wv.x, acc[ri][0]);
            acc[ri][1] = fmaf(h, wv.y, acc[ri][1]);
        }
    }
#pragma unroll
    for (int ri = 0; ri < 8; ri++) {
        int i = w + ri * 8;
        sH[i * 65 + c0]     = fmaxf(acc[ri][0] + sb1v[c0], 0.f);
        sH[i * 65 + c0 + 1] = fmaxf(acc[ri][1] + sb1v[c0 + 1], 0.f);
    }
    __syncthreads();
    int i = tid >> 2; int q0 = (tid & 3) * 3;
    float a0 = sb2v[q0], a1 = sb2v[q0 + 1], a2 = sb2v[q0 + 2];
#pragma unroll 8
    for (int k = 0; k < 64; k++) {
        float h = sH[i * 65 + k];
        a0 = fmaf(h, sW2[k * 12 + q0],     a0);
        a1 = fmaf(h, sW2[k * 12 + q0 + 1], a1);
        a2 = fmaf(h, sW2[k * 12 + q0 + 2], a2);
    }
    int r = row0 + i, b = r >> 10, n = r & 1023;
    out[(((size_t)b * Qk + q0)     << 10) + n] = a0;
    out[(((size_t)b * Qk + q0 + 1) << 10) + n] = a1;
    out[(((size_t)b * Qk + q0 + 2) << 10) + n] = a2;
}

// ---------------- launch ----------------
extern "C" void kernel_launch(void* const* d_in, const int* in_sizes, int n_in,
                              void* d_out, int out_size) {
    const float* X     = (const float*)d_in[0];
    const float* SE    = (const float*)d_in[3];
    const float* W_se1 = (const float*)d_in[4];  const float* b_se1 = (const float*)d_in[5];
    const float* W_se2 = (const float*)d_in[6];  const float* b_se2 = (const float*)d_in[7];
    const float* W_te1 = (const float*)d_in[8];  const float* b_te1 = (const float*)d_in[9];
    const float* W_te2 = (const float*)d_in[10]; const float* b_te2 = (const float*)d_in[11];
    const float* W_in1 = (const float*)d_in[12]; const float* b_in1 = (const float*)d_in[13];
    const float* W_in2 = (const float*)d_in[14]; const float* b_in2 = (const float*)d_in[15];
    const float* Wg1   = (const float*)d_in[16]; const float* bg1   = (const float*)d_in[17];
    const float* Wc1   = (const float*)d_in[18]; const float* bc1   = (const float*)d_in[19];
    const float* Wg2   = (const float*)d_in[20]; const float* bg2   = (const float*)d_in[21];
    const float* Wc2   = (const float*)d_in[22]; const float* bc2   = (const float*)d_in[23];
    const float* W_o1  = (const float*)d_in[24]; const float* b_o1  = (const float*)d_in[25];
    const float* W_o2  = (const float*)d_in[26]; const float* b_o2  = (const float*)d_in[27];
    const int*   TE    = (const int*)d_in[28];
    float* out = (float*)d_out;

    const size_t layer_smem = (size_t)37056 * 4;   // 148,224 B dynamic smem
    cudaFuncSetAttribute(k_layer, cudaFuncAttributeMaxDynamicSharedMemorySize,
                         (int)layer_smem);

    k_prep<<<48, 256>>>(Wg1, Wc1, Wg2, Wc2);
    k_se<<<Nk, 64>>>(SE, W_se1, b_se1, W_se2, b_se2);
    k_te<<<Bk * Pk, 64>>>(TE, W_te1, b_te1, W_te2, b_te2);
    k_fc_in<<<Bk * Pk * Nk / 64, 256>>>(X, W_in1, b_in1, W_in2, b_in2);

    k_layer<<<Bk * Nk / 64, 256, layer_smem>>>(0, bg1, bc1);
    k_layer<<<Bk * Nk / 64, 256, layer_smem>>>(1, bg2, bc2);

    k_fc_out<<<Bk * Nk / 64, 256>>>(W_o1, b_o1, W_o2, b_o2, out);
}

// round 4
// speedup vs baseline: 1.9024x; 1.0006x over previous
#include <cuda_runtime.h>

#define Bk 64
#define Pk 12
#define Qk 12
#define Nk 1024
#define Dk 64

typedef unsigned long long ull;

__device__ __forceinline__ ull ffma2(ull a, ull b, ull c) {
    ull d;
    asm("fma.rn.f32x2 %0, %1, %2, %3;" : "=l"(d) : "l"(a), "l"(b), "l"(c));
    return d;
}
__device__ __forceinline__ float2 u2f(ull a) {
    float2 f;
    asm("mov.b64 {%0, %1}, %2;" : "=f"(f.x), "=f"(f.y) : "l"(a));
    return f;
}
__device__ __forceinline__ float sigm(float z) {
    z = fminf(fmaxf(z, -30.f), 30.f);
    return __fdividef(1.f, 1.f + __expf(-z));
}
__device__ __forceinline__ float tanh_fast(float z) {
    z = fminf(fmaxf(z, -15.f), 15.f);
    float e = __expf(-2.f * z);
    return __fdividef(1.f - e, 1.f + e);
}

// ---------------- scratch (device globals; no allocations allowed) ----------------
__device__ float g_se[Nk * Dk];                       // spatial embedding  [N,D]
__device__ float g_te[Bk * Pk * Dk];                  // temporal embedding [B*P,D]
__device__ float g_Xe[(size_t)Bk * Pk * Nk * Dk];     // FC_in output       [B,P,N,D]
__device__ float g_seq1[(size_t)Bk * Pk * Nk * Dk];   // layer-1 sequence   [B,P,N,D]
__device__ float g_s2[Bk * Nk * Dk];                  // layer-2 final state[B,N,D]

// folded (support = I) weights, packed for f32x2:
// element at ((k>>1)*COLS + c)*2 + (k&1) = W[k][c], i.e. float2 holds (W[2k2][c], W[2k2+1][c])
__device__ float g_Wgx[2][64 * 128];   // gate, x-part     [k][128]
__device__ float g_Wgs[2][64 * 128];   // gate, s-part     [k][128]
__device__ float g_Wcx[2][64 * 64];    // candidate x-part [k][64]
__device__ float g_Wcs[2][64 * 64];    // candidate s-part [k][64]

// ---------------- weight folding + packing ----------------
__global__ void k_prep(const float* __restrict__ Wg1, const float* __restrict__ Wc1,
                       const float* __restrict__ Wg2, const float* __restrict__ Wc2) {
    int tid = blockIdx.x * blockDim.x + threadIdx.x;
    int stride = gridDim.x * blockDim.x;
    for (int idx = tid; idx < 64 * 128; idx += stride) {
        int k = idx >> 7, c = idx & 127;
        int d = ((k >> 1) * 128 + c) * 2 + (k & 1);
        g_Wgx[0][d] = Wg1[k * 128 + c] + Wg1[(128 + k) * 128 + c];
        g_Wgx[1][d] = Wg2[k * 128 + c] + Wg2[(128 + k) * 128 + c];
        g_Wgs[0][d] = Wg1[(64 + k) * 128 + c] + Wg1[(192 + k) * 128 + c];
        g_Wgs[1][d] = Wg2[(64 + k) * 128 + c] + Wg2[(192 + k) * 128 + c];
    }
    for (int idx = tid; idx < 64 * 64; idx += stride) {
        int k = idx >> 6, c = idx & 63;
        int d = ((k >> 1) * 64 + c) * 2 + (k & 1);
        g_Wcx[0][d] = Wc1[k * 64 + c] + Wc1[(128 + k) * 64 + c];
        g_Wcx[1][d] = Wc2[k * 64 + c] + Wc2[(128 + k) * 64 + c];
        g_Wcs[0][d] = Wc1[(64 + k) * 64 + c] + Wc1[(192 + k) * 64 + c];
        g_Wcs[1][d] = Wc2[(64 + k) * 64 + c] + Wc2[(192 + k) * 64 + c];
    }
}

// ---------------- spatial embedding: relu(SE@W1+b1)@W2+b2 ----------------
__global__ void k_se(const float* __restrict__ SE, const float* __restrict__ W1,
                     const float* __restrict__ b1, const float* __restrict__ W2,
                     const float* __restrict__ b2) {
    __shared__ float xs[64], hs[64];
    int n = blockIdx.x, d = threadIdx.x;
    xs[d] = SE[n * 64 + d];
    __syncthreads();
    float a = b1[d];
#pragma unroll 8
    for (int k = 0; k < 64; k++) a = fmaf(xs[k], W1[k * 64 + d], a);
    hs[d] = fmaxf(a, 0.f);
    __syncthreads();
    float o = b2[d];
#pragma unroll 8
    for (int k = 0; k < 64; k++) o = fmaf(hs[k], W2[k * 64 + d], o);
    g_se[n * 64 + d] = o;
}

// ---------------- temporal embedding (one-hot @ W = row gather) ----------------
__global__ void k_te(const int* __restrict__ TE, const float* __restrict__ W1,
                     const float* __restrict__ b1, const float* __restrict__ W2,
                     const float* __restrict__ b2) {
    __shared__ float hs[64];
    int row = blockIdx.x;              // b*P + p
    int b = row / Pk, p = row - b * Pk;
    int d = threadIdx.x;
    int base = (b * (Pk + Qk) + p) * 2;
    int t0 = TE[base], t1 = TE[base + 1];
    float a = W1[t0 * 64 + d] + W1[(7 + t1) * 64 + d] + b1[d];
    hs[d] = fmaxf(a, 0.f);
    __syncthreads();
    float o = b2[d];
#pragma unroll 8
    for (int k = 0; k < 64; k++) o = fmaf(hs[k], W2[k * 64 + d], o);
    g_te[row * 64 + d] = o;
}

// ---------------- FC_in: Xe = relu(x*W1+b1)@W2 + b2 + se + te (f32x2) ----------------
__global__ __launch_bounds__(256) void k_fc_in(const float* __restrict__ X,
    const float* __restrict__ W1, const float* __restrict__ b1,
    const float* __restrict__ W2, const float* __restrict__ b2) {
    __shared__ float sW2p[64 * 64];    // packed: ((k>>1)*64+c)*2 + (k&1)
    __shared__ float sH[64 * 64];
    __shared__ float sx[64];
    __shared__ float sw1[64], sb1[64], sb2[64];
    int tid = threadIdx.x;
    for (int i = tid; i < 4096; i += 256) {
        int k = i >> 6, c = i & 63;
        sW2p[((k >> 1) * 64 + c) * 2 + (k & 1)] = W2[i];
    }
    if (tid < 64) { sw1[tid] = W1[tid]; sb1[tid] = b1[tid]; sb2[tid] = b2[tid]; }
    int row0 = blockIdx.x * 64;
    if (tid >= 64 && tid < 128) sx[tid - 64] = X[row0 + tid - 64];
    __syncthreads();
    for (int idx = tid; idx < 4096; idx += 256) {
        int i = idx >> 6, d = idx & 63;
        sH[idx] = fmaxf(fmaf(sx[i], sw1[d], sb1[d]), 0.f);
    }
    __syncthreads();
    int lane = tid & 31, w = tid >> 5, c0 = lane * 2;
    const ull* W2p = (const ull*)sW2p;
    ull acc[8][2];
#pragma unroll
    for (int ri = 0; ri < 8; ri++) { acc[ri][0] = 0ULL; acc[ri][1] = 0ULL; }
#pragma unroll 4
    for (int k2 = 0; k2 < 32; k2++) {
        ulonglong2 wv = *(const ulonglong2*)&W2p[k2 * 64 + c0];
#pragma unroll
        for (int ri = 0; ri < 8; ri++) {
            ull hv = *(const ull*)&sH[(w + ri * 8) * 64 + 2 * k2];
            acc[ri][0] = ffma2(hv, wv.x, acc[ri][0]);
            acc[ri][1] = ffma2(hv, wv.y, acc[ri][1]);
        }
    }
#pragma unroll
    for (int ri = 0; ri < 8; ri++) {
        int i = w + ri * 8; int r = row0 + i;
        int n = r & (Nk - 1); int bp = r >> 10;
        float2 p0 = u2f(acc[ri][0]), p1 = u2f(acc[ri][1]);
        float o0 = p0.x + p0.y + sb2[c0]     + g_se[n * 64 + c0]     + g_te[bp * 64 + c0];
        float o1 = p1.x + p1.y + sb2[c0 + 1] + g_se[n * 64 + c0 + 1] + g_te[bp * 64 + c0 + 1];
        *(float2*)&g_Xe[(size_t)r * 64 + c0] = make_float2(o0, o1);
    }
}

// ---------------- persistent DCGRU layer: all 12 steps in one kernel ----------------
// smem (floats): sWgx[8192] sWgs[8192] sWcx[4096] sWcs[4096] sX[4096] sS[4096] sR[4096] sbg[128] sbc[64]
__global__ __launch_bounds__(256, 1) void k_layer(int layer,
        const float* __restrict__ bg, const float* __restrict__ bc) {
    extern __shared__ float sm[];
    float* sWgx = sm;
    float* sWgs = sm + 8192;
    float* sWcx = sm + 16384;
    float* sWcs = sm + 20480;
    float* sX   = sm + 24576;
    float* sS   = sm + 28672;
    float* sR   = sm + 32768;
    float* sbg  = sm + 36864;
    float* sbc  = sm + 36992;

    int tid = threadIdx.x;
    {
        const float4* a = (const float4*)g_Wgx[layer];
        const float4* b = (const float4*)g_Wgs[layer];
        float4* da = (float4*)sWgx; float4* db = (float4*)sWgs;
        for (int i = tid; i < 2048; i += 256) { da[i] = a[i]; db[i] = b[i]; }
        const float4* c = (const float4*)g_Wcx[layer];
        const float4* d = (const float4*)g_Wcs[layer];
        float4* dc = (float4*)sWcx; float4* dd = (float4*)sWcs;
        for (int i = tid; i < 1024; i += 256) { dc[i] = c[i]; dd[i] = d[i]; }
    }
    if (tid < 128) sbg[tid] = bg[tid];
    if (tid < 64)  sbc[tid] = bc[tid];
    for (int i = tid; i < 4096; i += 256) sS[i] = 0.f;

    int row0 = blockIdx.x * 64;
    int b = row0 >> 10; int n0 = row0 & 1023;
    const float* Xbase = (layer == 0) ? g_Xe : g_seq1;
    {
        const float4* x0 = (const float4*)&Xbase[((size_t)(b * Pk) * Nk + n0) * 64];
        float4* d = (float4*)sX;
#pragma unroll
        for (int q = 0; q < 4; q++) d[tid + q * 256] = x0[tid + q * 256];
    }
    __syncthreads();

    int lane = tid & 31, w = tid >> 5, j0 = lane * 2;
    const ull* Wgx2 = (const ull*)sWgx;
    const ull* Wgs2 = (const ull*)sWgs;
    const ull* Wcx2 = (const ull*)sWcx;
    const ull* Wcs2 = (const ull*)sWcs;
    float4 pre[4];

    for (int t = 0; t < Pk; t++) {
        // prefetch next x tile (overlaps phase-A compute)
        if (t + 1 < Pk) {
            const float4* xs = (const float4*)&Xbase[((size_t)(b * Pk + t + 1) * Nk + n0) * 64];
#pragma unroll
            for (int q = 0; q < 4; q++) pre[q] = xs[tid + q * 256];
        }

        // ---- phase A: gates (128 cols: r at j0, u at 64+j0) ----
        ull accA[8][4];
#pragma unroll
        for (int ri = 0; ri < 8; ri++) {
            accA[ri][0] = 0ULL; accA[ri][1] = 0ULL; accA[ri][2] = 0ULL; accA[ri][3] = 0ULL;
        }
#pragma unroll 2
        for (int kk = 0; kk < 16; kk++) {
            ulonglong2 wrx0 = *(const ulonglong2*)&Wgx2[(2 * kk) * 128 + j0];
            ulonglong2 wux0 = *(const ulonglong2*)&Wgx2[(2 * kk) * 128 + 64 + j0];
            ulonglong2 wrs0 = *(const ulonglong2*)&Wgs2[(2 * kk) * 128 + j0];
            ulonglong2 wus0 = *(const ulonglong2*)&Wgs2[(2 * kk) * 128 + 64 + j0];
            ulonglong2 wrx1 = *(const ulonglong2*)&Wgx2[(2 * kk + 1) * 128 + j0];
            ulonglong2 wux1 = *(const ulonglong2*)&Wgx2[(2 * kk + 1) * 128 + 64 + j0];
            ulonglong2 wrs1 = *(const ulonglong2*)&Wgs2[(2 * kk + 1) * 128 + j0];
            ulonglong2 wus1 = *(const ulonglong2*)&Wgs2[(2 * kk + 1) * 128 + 64 + j0];
#pragma unroll
            for (int ri = 0; ri < 8; ri++) {
                int i = w + ri * 8;
                ulonglong2 xv = *(const ulonglong2*)&sX[i * 64 + 4 * kk];
                ulonglong2 sv = *(const ulonglong2*)&sS[i * 64 + 4 * kk];
                accA[ri][0] = ffma2(xv.x, wrx0.x, accA[ri][0]);
                accA[ri][1] = ffma2(xv.x, wrx0.y, accA[ri][1]);
                accA[ri][2] = ffma2(xv.x, wux0.x, accA[ri][2]);
                accA[ri][3] = ffma2(xv.x, wux0.y, accA[ri][3]);
                accA[ri][0] = ffma2(sv.x, wrs0.x, accA[ri][0]);
                accA[ri][1] = ffma2(sv.x, wrs0.y, accA[ri][1]);
                accA[ri][2] = ffma2(sv.x, wus0.x, accA[ri][2]);
                accA[ri][3] = ffma2(sv.x, wus0.y, accA[ri][3]);
                accA[ri][0] = ffma2(xv.y, wrx1.x, accA[ri][0]);
                accA[ri][1] = ffma2(xv.y, wrx1.y, accA[ri][1]);
                accA[ri][2] = ffma2(xv.y, wux1.x, accA[ri][2]);
                accA[ri][3] = ffma2(xv.y, wux1.y, accA[ri][3]);
                accA[ri][0] = ffma2(sv.y, wrs1.x, accA[ri][0]);
                accA[ri][1] = ffma2(sv.y, wrs1.y, accA[ri][1]);
                accA[ri][2] = ffma2(sv.y, wus1.x, accA[ri][2]);
                accA[ri][3] = ffma2(sv.y, wus1.y, accA[ri][3]);
            }
        }
        float ur[8][2];
#pragma unroll
        for (int ri = 0; ri < 8; ri++) {
            int i = w + ri * 8;
            float2 p0 = u2f(accA[ri][0]), p1 = u2f(accA[ri][1]);
            float r0 = sigm(p0.x + p0.y + sbg[j0]);
            float r1 = sigm(p1.x + p1.y + sbg[j0 + 1]);
            float2 p2 = u2f(accA[ri][2]), p3 = u2f(accA[ri][3]);
            ur[ri][0] = sigm(p2.x + p2.y + sbg[64 + j0]);
            ur[ri][1] = sigm(p3.x + p3.y + sbg[64 + j0 + 1]);
            float2 sv = *(const float2*)&sS[i * 64 + j0];
            *(float2*)&sR[i * 64 + j0] = make_float2(r0 * sv.x, r1 * sv.y);
        }
        __syncthreads();

        // ---- phase B: candidate (64 cols) ----
        ull accB[8][2];
#pragma unroll
        for (int ri = 0; ri < 8; ri++) { accB[ri][0] = 0ULL; accB[ri][1] = 0ULL; }
#pragma unroll 2
        for (int kk = 0; kk < 16; kk++) {
            ulonglong2 wx0 = *(const ulonglong2*)&Wcx2[(2 * kk) * 64 + j0];
            ulonglong2 wc0 = *(const ulonglong2*)&Wcs2[(2 * kk) * 64 + j0];
            ulonglong2 wx1 = *(const ulonglong2*)&Wcx2[(2 * kk + 1) * 64 + j0];
            ulonglong2 wc1 = *(const ulonglong2*)&Wcs2[(2 * kk + 1) * 64 + j0];
#pragma unroll
            for (int ri = 0; ri < 8; ri++) {
                int i = w + ri * 8;
                ulonglong2 xv = *(const ulonglong2*)&sX[i * 64 + 4 * kk];
                ulonglong2 rv = *(const ulonglong2*)&sR[i * 64 + 4 * kk];
                accB[ri][0] = ffma2(xv.x, wx0.x, accB[ri][0]);
                accB[ri][1] = ffma2(xv.x, wx0.y, accB[ri][1]);
                accB[ri][0] = ffma2(rv.x, wc0.x, accB[ri][0]);
                accB[ri][1] = ffma2(rv.x, wc0.y, accB[ri][1]);
                accB[ri][0] = ffma2(xv.y, wx1.x, accB[ri][0]);
                accB[ri][1] = ffma2(xv.y, wx1.y, accB[ri][1]);
                accB[ri][0] = ffma2(rv.y, wc1.x, accB[ri][0]);
                accB[ri][1] = ffma2(rv.y, wc1.y, accB[ri][1]);
            }
        }
        __syncthreads();   // all warps done reading sX/sR

        // install prefetched x(t+1)
        if (t + 1 < Pk) {
            float4* d = (float4*)sX;
#pragma unroll
            for (int q = 0; q < 4; q++) d[tid + q * 256] = pre[q];
        }

        // ---- epilogue: c = tanh(...), new = u*s + (1-u)*c ----
        float* out = (layer == 0)
            ? &g_seq1[((size_t)(b * Pk + t) * Nk + n0) * 64] : (float*)0;
#pragma unroll
        for (int ri = 0; ri < 8; ri++) {
            int i = w + ri * 8;
            float2 pc0 = u2f(accB[ri][0]), pc1 = u2f(accB[ri][1]);
            float c0v = tanh_fast(pc0.x + pc0.y + sbc[j0]);
            float c1v = tanh_fast(pc1.x + pc1.y + sbc[j0 + 1]);
            float2 sv = *(const float2*)&sS[i * 64 + j0];
            float nv0 = fmaf(ur[ri][0], sv.x - c0v, c0v);
            float nv1 = fmaf(ur[ri][1], sv.y - c1v, c1v);
            *(float2*)&sS[i * 64 + j0] = make_float2(nv0, nv1);
            if (out) *(float2*)&out[i * 64 + j0] = make_float2(nv0, nv1);
        }
        __syncthreads();
    }

    if (layer == 1) {
        float4* d = (float4*)&g_s2[(size_t)row0 * 64];
        const float4* s = (const float4*)sS;
#pragma unroll
        for (int q = 0; q < 4; q++) d[tid + q * 256] = s[tid + q * 256];
    }
}

// ---------------- FC_out: y = relu(h@Wo1+bo1)@Wo2+bo2; out[b,q,n] ----------------
__global__ __launch_bounds__(256) void k_fc_out(
        const float* __restrict__ W1, const float* __restrict__ b1,
        const float* __restrict__ W2, const float* __restrict__ b2,
        float* __restrict__ out) {
    __shared__ float sW1[64 * 64];
    __shared__ float sHin[64 * 64];
    __shared__ float sH[64 * 65];
    __shared__ float sW2[64 * 12];
    __shared__ float sb1v[64], sb2v[12];
    int tid = threadIdx.x;
    for (int i = tid; i < 4096; i += 256) sW1[i] = W1[i];
    for (int i = tid; i < 768; i += 256) sW2[i] = W2[i];
    if (tid < 64) sb1v[tid] = b1[tid];
    if (tid < 12) sb2v[tid] = b2[tid];
    int row0 = blockIdx.x * 64;
    for (int i4 = tid; i4 < 1024; i4 += 256) {
        int i = i4 >> 4, c = (i4 & 15) << 2;
        *(float4*)&sHin[i * 64 + c] = *(const float4*)&g_s2[(size_t)(row0 + i) * 64 + c];
    }
    __syncthreads();
    int lane = tid & 31, w = tid >> 5, c0 = lane * 2;
    float acc[8][2];
#pragma unroll
    for (int ri = 0; ri < 8; ri++) { acc[ri][0] = 0.f; acc[ri][1] = 0.f; }
#pragma unroll 8
    for (int k = 0; k < 64; k++) {
        float2 wv = *(const float2*)&sW1[k * 64 + c0];
#pragma unroll
        for (int ri = 0; ri < 8; ri++) {
            float h = sHin[(w + ri * 8) * 64 + k];
            acc[ri][0] = fmaf(h, wv.x, acc[ri][0]);
            acc[ri][1] = fmaf(h, wv.y, acc[ri][1]);
        }
    }
#pragma unroll
    for (int ri = 0; ri < 8; ri++) {
        int i = w + ri * 8;
        sH[i * 65 + c0]     = fmaxf(acc[ri][0] + sb1v[c0], 0.f);
        sH[i * 65 + c0 + 1] = fmaxf(acc[ri][1] + sb1v[c0 + 1], 0.f);
    }
    __syncthreads();
    int i = tid >> 2; int q0 = (tid & 3) * 3;
    float a0 = sb2v[q0], a1 = sb2v[q0 + 1], a2 = sb2v[q0 + 2];
#pragma unroll 8
    for (int k = 0; k < 64; k++) {
        float h = sH[i * 65 + k];
        a0 = fmaf(h, sW2[k * 12 + q0],     a0);
        a1 = fmaf(h, sW2[k * 12 + q0 + 1], a1);
        a2 = fmaf(h, sW2[k * 12 + q0 + 2], a2);
    }
    int r = row0 + i, b = r >> 10, n = r & 1023;
    out[(((size_t)b * Qk + q0)     << 10) + n] = a0;
    out[(((size_t)b * Qk + q0 + 1) << 10) + n] = a1;
    out[(((size_t)b * Qk + q0 + 2) << 10) + n] = a2;
}

// ---------------- launch ----------------
extern "C" void kernel_launch(void* const* d_in, const int* in_sizes, int n_in,
                              void* d_out, int out_size) {
    const float* X     = (const float*)d_in[0];
    const float* SE    = (const float*)d_in[3];
    const float* W_se1 = (const float*)d_in[4];  const float* b_se1 = (const float*)d_in[5];
    const float* W_se2 = (const float*)d_in[6];  const float* b_se2 = (const float*)d_in[7];
    const float* W_te1 = (const float*)d_in[8];  const float* b_te1 = (const float*)d_in[9];
    const float* W_te2 = (const float*)d_in[10]; const float* b_te2 = (const float*)d_in[11];
    const float* W_in1 = (const float*)d_in[12]; const float* b_in1 = (const float*)d_in[13];
    const float* W_in2 = (const float*)d_in[14]; const float* b_in2 = (const float*)d_in[15];
    const float* Wg1   = (const float*)d_in[16]; const float* bg1   = (const float*)d_in[17];
    const float* Wc1   = (const float*)d_in[18]; const float* bc1   = (const float*)d_in[19];
    const float* Wg2   = (const float*)d_in[20]; const float* bg2   = (const float*)d_in[21];
    const float* Wc2   = (const float*)d_in[22]; const float* bc2   = (const float*)d_in[23];
    const float* W_o1  = (const float*)d_in[24]; const float* b_o1  = (const float*)d_in[25];
    const float* W_o2  = (const float*)d_in[26]; const float* b_o2  = (const float*)d_in[27];
    const int*   TE    = (const int*)d_in[28];
    float* out = (float*)d_out;

    const size_t layer_smem = (size_t)37056 * 4;   // 148,224 B dynamic smem
    cudaFuncSetAttribute(k_layer, cudaFuncAttributeMaxDynamicSharedMemorySize,
                         (int)layer_smem);

    k_prep<<<48, 256>>>(Wg1, Wc1, Wg2, Wc2);
    k_se<<<Nk, 64>>>(SE, W_se1, b_se1, W_se2, b_se2);
    k_te<<<Bk * Pk, 64>>>(TE, W_te1, b_te1, W_te2, b_te2);
    k_fc_in<<<Bk * Pk * Nk / 64, 256>>>(X, W_in1, b_in1, W_in2, b_in2);

    k_layer<<<Bk * Nk / 64, 256, layer_smem>>>(0, bg1, bc1);
    k_layer<<<Bk * Nk / 64, 256, layer_smem>>>(1, bg2, bc2);

    k_fc_out<<<Bk * Nk / 64, 256>>>(W_o1, b_o1, W_o2, b_o2, out);
}

// round 5
// speedup vs baseline: 4.0522x; 2.1300x over previous
#include <cuda_runtime.h>

#define Bk 64
#define Pk 12
#define Qk 12
#define Nk 1024
#define Dk 64

typedef unsigned long long ull;
typedef unsigned int uint32;

__device__ __forceinline__ ull ffma2(ull a, ull b, ull c) {
    ull d;
    asm("fma.rn.f32x2 %0, %1, %2, %3;" : "=l"(d) : "l"(a), "l"(b), "l"(c));
    return d;
}
__device__ __forceinline__ float2 u2f(ull a) {
    float2 f;
    asm("mov.b64 {%0, %1}, %2;" : "=f"(f.x), "=f"(f.y) : "l"(a));
    return f;
}
__device__ __forceinline__ float sigm(float z) {
    z = fminf(fmaxf(z, -30.f), 30.f);
    return __fdividef(1.f, 1.f + __expf(-z));
}
__device__ __forceinline__ float tanh_fast(float z) {
    z = fminf(fmaxf(z, -15.f), 15.f);
    float e = __expf(-2.f * z);
    return __fdividef(1.f - e, 1.f + e);
}
__device__ __forceinline__ uint32 tf32c(float f) {
    uint32 u;
    asm("cvt.rna.tf32.f32 %0, %1;" : "=r"(u) : "f"(f));
    return u;
}
__device__ __forceinline__ void mma_tf32(float* d, const uint32* a, uint32 b0, uint32 b1) {
    asm("mma.sync.aligned.m16n8k8.row.col.f32.tf32.tf32.f32 "
        "{%0,%1,%2,%3},{%4,%5,%6,%7},{%8,%9},{%0,%1,%2,%3};"
        : "+f"(d[0]), "+f"(d[1]), "+f"(d[2]), "+f"(d[3])
        : "r"(a[0]), "r"(a[1]), "r"(a[2]), "r"(a[3]), "r"(b0), "r"(b1));
}

// ---------------- scratch (device globals; no allocations allowed) ----------------
__device__ float g_se[Nk * Dk];
__device__ float g_te[Bk * Pk * Dk];
__device__ float g_Xe[(size_t)Bk * Pk * Nk * Dk];
__device__ float g_seq1[(size_t)Bk * Pk * Nk * Dk];
__device__ float g_s2[Bk * Nk * Dk];

// mma B-fragment packed, tf32-converted, support-folded weights.
// gates:  g_gBW[layer][part(0=x,1=s)][nt(16)][kt(8)][lane(32)][2]
// cand :  g_cBW[layer][part(0=x,1=rs)][nt(8)][kt(8)][lane(32)][2]
__device__ float g_gBW[2][16384];
__device__ float g_cBW[2][8192];

// ---------------- weight folding + fragment packing (tf32) ----------------
__global__ void k_prep(const float* __restrict__ Wg1, const float* __restrict__ Wc1,
                       const float* __restrict__ Wg2, const float* __restrict__ Wc2) {
    int tid = blockIdx.x * blockDim.x + threadIdx.x;
    int stride = gridDim.x * blockDim.x;
    // gates: 2 layers x 2 parts x 16 nt x 8 kt x 32 lanes
    for (int i = tid; i < 2 * 2 * 16 * 8 * 32; i += stride) {
        int lane = i & 31;
        int kt   = (i >> 5) & 7;
        int nt   = (i >> 8) & 15;
        int part = (i >> 12) & 1;
        int l    = (i >> 13) & 1;
        int g = lane >> 2, tig = lane & 3;
        int k0 = kt * 8 + tig;
        int n  = nt * 8 + g;
        const float* W = l ? Wg2 : Wg1;
        int r0 = part ? 64 : 0;
        float b0 = W[(r0 + k0) * 128 + n]       + W[(r0 + 128 + k0) * 128 + n];
        float b1 = W[(r0 + k0 + 4) * 128 + n]   + W[(r0 + 128 + k0 + 4) * 128 + n];
        float* dst = &g_gBW[l][((part * 16 + nt) * 8 + kt) * 64 + lane * 2];
        dst[0] = __uint_as_float(tf32c(b0));
        dst[1] = __uint_as_float(tf32c(b1));
    }
    // candidate: 2 layers x 2 parts x 8 nt x 8 kt x 32 lanes
    for (int i = tid; i < 2 * 2 * 8 * 8 * 32; i += stride) {
        int lane = i & 31;
        int kt   = (i >> 5) & 7;
        int nt   = (i >> 8) & 7;
        int part = (i >> 11) & 1;
        int l    = (i >> 12) & 1;
        int g = lane >> 2, tig = lane & 3;
        int k0 = kt * 8 + tig;
        int n  = nt * 8 + g;
        const float* W = l ? Wc2 : Wc1;
        int r0 = part ? 64 : 0;
        float b0 = W[(r0 + k0) * 64 + n]       + W[(r0 + 128 + k0) * 64 + n];
        float b1 = W[(r0 + k0 + 4) * 64 + n]   + W[(r0 + 128 + k0 + 4) * 64 + n];
        float* dst = &g_cBW[l][((part * 8 + nt) * 8 + kt) * 64 + lane * 2];
        dst[0] = __uint_as_float(tf32c(b0));
        dst[1] = __uint_as_float(tf32c(b1));
    }
}

// ---------------- spatial embedding ----------------
__global__ void k_se(const float* __restrict__ SE, const float* __restrict__ W1,
                     const float* __restrict__ b1, const float* __restrict__ W2,
                     const float* __restrict__ b2) {
    __shared__ float xs[64], hs[64];
    int n = blockIdx.x, d = threadIdx.x;
    xs[d] = SE[n * 64 + d];
    __syncthreads();
    float a = b1[d];
#pragma unroll 8
    for (int k = 0; k < 64; k++) a = fmaf(xs[k], W1[k * 64 + d], a);
    hs[d] = fmaxf(a, 0.f);
    __syncthreads();
    float o = b2[d];
#pragma unroll 8
    for (int k = 0; k < 64; k++) o = fmaf(hs[k], W2[k * 64 + d], o);
    g_se[n * 64 + d] = o;
}

// ---------------- temporal embedding ----------------
__global__ void k_te(const int* __restrict__ TE, const float* __restrict__ W1,
                     const float* __restrict__ b1, const float* __restrict__ W2,
                     const float* __restrict__ b2) {
    __shared__ float hs[64];
    int row = blockIdx.x;
    int b = row / Pk, p = row - b * Pk;
    int d = threadIdx.x;
    int base = (b * (Pk + Qk) + p) * 2;
    int t0 = TE[base], t1 = TE[base + 1];
    float a = W1[t0 * 64 + d] + W1[(7 + t1) * 64 + d] + b1[d];
    hs[d] = fmaxf(a, 0.f);
    __syncthreads();
    float o = b2[d];
#pragma unroll 8
    for (int k = 0; k < 64; k++) o = fmaf(hs[k], W2[k * 64 + d], o);
    g_te[row * 64 + d] = o;
}

// ---------------- FC_in (f32x2 scalar) ----------------
__global__ __launch_bounds__(256) void k_fc_in(const float* __restrict__ X,
    const float* __restrict__ W1, const float* __restrict__ b1,
    const float* __restrict__ W2, const float* __restrict__ b2) {
    __shared__ float sW2p[64 * 64];
    __shared__ float sH[64 * 64];
    __shared__ float sx[64];
    __shared__ float sw1[64], sb1[64], sb2[64];
    int tid = threadIdx.x;
    for (int i = tid; i < 4096; i += 256) {
        int k = i >> 6, c = i & 63;
        sW2p[((k >> 1) * 64 + c) * 2 + (k & 1)] = W2[i];
    }
    if (tid < 64) { sw1[tid] = W1[tid]; sb1[tid] = b1[tid]; sb2[tid] = b2[tid]; }
    int row0 = blockIdx.x * 64;
    if (tid >= 64 && tid < 128) sx[tid - 64] = X[row0 + tid - 64];
    __syncthreads();
    for (int idx = tid; idx < 4096; idx += 256) {
        int i = idx >> 6, d = idx & 63;
        sH[idx] = fmaxf(fmaf(sx[i], sw1[d], sb1[d]), 0.f);
    }
    __syncthreads();
    int lane = tid & 31, w = tid >> 5, c0 = lane * 2;
    const ull* W2p = (const ull*)sW2p;
    ull acc[8][2];
#pragma unroll
    for (int ri = 0; ri < 8; ri++) { acc[ri][0] = 0ULL; acc[ri][1] = 0ULL; }
#pragma unroll 4
    for (int k2 = 0; k2 < 32; k2++) {
        ulonglong2 wv = *(const ulonglong2*)&W2p[k2 * 64 + c0];
#pragma unroll
        for (int ri = 0; ri < 8; ri++) {
            ull hv = *(const ull*)&sH[(w + ri * 8) * 64 + 2 * k2];
            acc[ri][0] = ffma2(hv, wv.x, acc[ri][0]);
            acc[ri][1] = ffma2(hv, wv.y, acc[ri][1]);
        }
    }
#pragma unroll
    for (int ri = 0; ri < 8; ri++) {
        int i = w + ri * 8; int r = row0 + i;
        int n = r & (Nk - 1); int bp = r >> 10;
        float2 p0 = u2f(acc[ri][0]), p1 = u2f(acc[ri][1]);
        float o0 = p0.x + p0.y + sb2[c0]     + g_se[n * 64 + c0]     + g_te[bp * 64 + c0];
        float o1 = p1.x + p1.y + sb2[c0 + 1] + g_se[n * 64 + c0 + 1] + g_te[bp * 64 + c0 + 1];
        *(float2*)&g_Xe[(size_t)r * 64 + c0] = make_float2(o0, o1);
    }
}

// ---------------- persistent DCGRU layer: tf32 tensor-core scan ----------------
// smem floats: gW[16384] cW[8192] sbg[128] sbc[64] sX[4352] sS[4352] sR[4352] sU[4352]
#define RP 68   // padded row stride (floats) -> bank = (4g+tig)%32, conflict-free
__global__ __launch_bounds__(256, 1) void k_layer(int layer,
        const float* __restrict__ bg, const float* __restrict__ bc) {
    extern __shared__ float sm[];
    float* gW  = sm;               // 16384
    float* cW  = sm + 16384;       // 8192
    float* sbg = sm + 24576;       // 128
    float* sbc = sm + 24704;       // 64
    float* sX  = sm + 24768;       // 4352
    float* sS  = sm + 29120;       // 4352
    float* sR  = sm + 33472;       // 4352
    float* sU  = sm + 37824;       // 4352

    int tid = threadIdx.x;
    {
        const float4* a = (const float4*)g_gBW[layer];
        float4* da = (float4*)gW;
        for (int i = tid; i < 4096; i += 256) da[i] = a[i];
        const float4* c = (const float4*)g_cBW[layer];
        float4* dc = (float4*)cW;
        for (int i = tid; i < 2048; i += 256) dc[i] = c[i];
    }
    if (tid < 128) sbg[tid] = bg[tid];
    if (tid < 64)  sbc[tid] = bc[tid];
    for (int i = tid; i < 4352; i += 256) sS[i] = 0.f;

    int row0 = blockIdx.x * 64;
    int b = row0 >> 10; int n0 = row0 & 1023;
    const float* Xbase = (layer == 0) ? g_Xe : g_seq1;

    // install x(0), tf32-converted
    {
        const float4* x0 = (const float4*)&Xbase[((size_t)(b * Pk) * Nk + n0) * 64];
#pragma unroll
        for (int q = 0; q < 4; q++) {
            int flat = tid + q * 256;
            float4 v = x0[flat];
            int row = flat >> 4, c = (flat & 15) << 2;
            float4 o;
            o.x = __uint_as_float(tf32c(v.x));
            o.y = __uint_as_float(tf32c(v.y));
            o.z = __uint_as_float(tf32c(v.z));
            o.w = __uint_as_float(tf32c(v.w));
            *(float4*)&sX[row * RP + c] = o;
        }
    }
    __syncthreads();

    int lane = tid & 31, w = tid >> 5;
    int g = lane >> 2, tig = lane & 3;
    int mp = w & 1, nq = w >> 1;       // mp: mtile pair, nq: n-quad
    float4 pre[4];

    for (int t = 0; t < Pk; t++) {
        if (t + 1 < Pk) {
            const float4* xs = (const float4*)&Xbase[((size_t)(b * Pk + t + 1) * Nk + n0) * 64];
#pragma unroll
            for (int q = 0; q < 4; q++) pre[q] = xs[tid + q * 256];
        }

        // ---- phase A: gates M=64 (2 mtiles/warp), N=128 (4 ntiles/warp), K=64 x {x,s}
        float accA[2][4][4];
#pragma unroll
        for (int mt = 0; mt < 2; mt++)
#pragma unroll
            for (int nt = 0; nt < 4; nt++)
#pragma unroll
                for (int v = 0; v < 4; v++) accA[mt][nt][v] = 0.f;

#pragma unroll
        for (int kt = 0; kt < 8; kt++) {
            uint32 ax[2][4], as_[2][4];
#pragma unroll
            for (int mt = 0; mt < 2; mt++) {
                int rb = (2 * mp + mt) * 16;
                int base = (rb + g) * RP + kt * 8 + tig;
                ax[mt][0] = __float_as_uint(sX[base]);
                ax[mt][1] = __float_as_uint(sX[base + 8 * RP]);
                ax[mt][2] = __float_as_uint(sX[base + 4]);
                ax[mt][3] = __float_as_uint(sX[base + 8 * RP + 4]);
                as_[mt][0] = tf32c(sS[base]);
                as_[mt][1] = tf32c(sS[base + 8 * RP]);
                as_[mt][2] = tf32c(sS[base + 4]);
                as_[mt][3] = tf32c(sS[base + 8 * RP + 4]);
            }
#pragma unroll
            for (int nt = 0; nt < 4; nt++) {
                int ntg = nq * 4 + nt;
                uint2 bx = *(const uint2*)&gW[(ntg * 8 + kt) * 64 + lane * 2];
                uint2 bs = *(const uint2*)&gW[8192 + (ntg * 8 + kt) * 64 + lane * 2];
#pragma unroll
                for (int mt = 0; mt < 2; mt++) {
                    mma_tf32(accA[mt][nt], ax[mt], bx.x, bx.y);
                    mma_tf32(accA[mt][nt], as_[mt], bs.x, bs.y);
                }
            }
        }
        // epilogue A: sigmoid; nq<2 -> r*s (tf32) into sR; nq>=2 -> u into sU
#pragma unroll
        for (int mt = 0; mt < 2; mt++) {
            int rb = (2 * mp + mt) * 16;
            int r0r = rb + g, r1r = rb + g + 8;
#pragma unroll
            for (int nt = 0; nt < 4; nt++) {
                int j = nq * 32 + nt * 8 + 2 * tig;
                float e0 = sigm(accA[mt][nt][0] + sbg[j]);
                float e1 = sigm(accA[mt][nt][1] + sbg[j + 1]);
                float e2 = sigm(accA[mt][nt][2] + sbg[j]);
                float e3 = sigm(accA[mt][nt][3] + sbg[j + 1]);
                if (nq < 2) {
                    sR[r0r * RP + j]     = __uint_as_float(tf32c(e0 * sS[r0r * RP + j]));
                    sR[r0r * RP + j + 1] = __uint_as_float(tf32c(e1 * sS[r0r * RP + j + 1]));
                    sR[r1r * RP + j]     = __uint_as_float(tf32c(e2 * sS[r1r * RP + j]));
                    sR[r1r * RP + j + 1] = __uint_as_float(tf32c(e3 * sS[r1r * RP + j + 1]));
                } else {
                    int ju = j - 64;
                    sU[r0r * RP + ju]     = e0;
                    sU[r0r * RP + ju + 1] = e1;
                    sU[r1r * RP + ju]     = e2;
                    sU[r1r * RP + ju + 1] = e3;
                }
            }
        }
        __syncthreads();

        // ---- phase B: candidate M=64, N=64 (2 ntiles/warp), K=64 x {x, r*s}
        float accB[2][2][4];
#pragma unroll
        for (int mt = 0; mt < 2; mt++)
#pragma unroll
            for (int nt = 0; nt < 2; nt++)
#pragma unroll
                for (int v = 0; v < 4; v++) accB[mt][nt][v] = 0.f;

#pragma unroll
        for (int kt = 0; kt < 8; kt++) {
            uint32 ax[2][4], ar[2][4];
#pragma unroll
            for (int mt = 0; mt < 2; mt++) {
                int rb = (2 * mp + mt) * 16;
                int base = (rb + g) * RP + kt * 8 + tig;
                ax[mt][0] = __float_as_uint(sX[base]);
                ax[mt][1] = __float_as_uint(sX[base + 8 * RP]);
                ax[mt][2] = __float_as_uint(sX[base + 4]);
                ax[mt][3] = __float_as_uint(sX[base + 8 * RP + 4]);
                ar[mt][0] = __float_as_uint(sR[base]);
                ar[mt][1] = __float_as_uint(sR[base + 8 * RP]);
                ar[mt][2] = __float_as_uint(sR[base + 4]);
                ar[mt][3] = __float_as_uint(sR[base + 8 * RP + 4]);
            }
#pragma unroll
            for (int nt = 0; nt < 2; nt++) {
                int ntg = nq * 2 + nt;
                uint2 bx = *(const uint2*)&cW[(ntg * 8 + kt) * 64 + lane * 2];
                uint2 bs = *(const uint2*)&cW[4096 + (ntg * 8 + kt) * 64 + lane * 2];
#pragma unroll
                for (int mt = 0; mt < 2; mt++) {
                    mma_tf32(accB[mt][nt], ax[mt], bx.x, bx.y);
                    mma_tf32(accB[mt][nt], ar[mt], bs.x, bs.y);
                }
            }
        }
        __syncthreads();   // all frag loads of sX/sR done

        // install prefetched x(t+1), tf32-converted
        if (t + 1 < Pk) {
#pragma unroll
            for (int q = 0; q < 4; q++) {
                int flat = tid + q * 256;
                int row = flat >> 4, c = (flat & 15) << 2;
                float4 v = pre[q];
                float4 o;
                o.x = __uint_as_float(tf32c(v.x));
                o.y = __uint_as_float(tf32c(v.y));
                o.z = __uint_as_float(tf32c(v.z));
                o.w = __uint_as_float(tf32c(v.w));
                *(float4*)&sX[row * RP + c] = o;
            }
        }

        // epilogue B: c = tanh(.), new = u*s + (1-u)*c -> sS (exact) + seq out
        float* outb = (layer == 0)
            ? &g_seq1[((size_t)(b * Pk + t) * Nk + n0) * 64] : (float*)0;
#pragma unroll
        for (int mt = 0; mt < 2; mt++) {
            int rb = (2 * mp + mt) * 16;
            int r0r = rb + g, r1r = rb + g + 8;
#pragma unroll
            for (int nt = 0; nt < 2; nt++) {
                int j = nq * 16 + nt * 8 + 2 * tig;
                float c0v = tanh_fast(accB[mt][nt][0] + sbc[j]);
                float c1v = tanh_fast(accB[mt][nt][1] + sbc[j + 1]);
                float c2v = tanh_fast(accB[mt][nt][2] + sbc[j]);
                float c3v = tanh_fast(accB[mt][nt][3] + sbc[j + 1]);
                float u0 = sU[r0r * RP + j],     s0 = sS[r0r * RP + j];
                float u1 = sU[r0r * RP + j + 1], s1 = sS[r0r * RP + j + 1];
                float u2 = sU[r1r * RP + j],     s2 = sS[r1r * RP + j];
                float u3 = sU[r1r * RP + j + 1], s3 = sS[r1r * RP + j + 1];
                float n0v = fmaf(u0, s0 - c0v, c0v);
                float n1v = fmaf(u1, s1 - c1v, c1v);
                float n2v = fmaf(u2, s2 - c2v, c2v);
                float n3v = fmaf(u3, s3 - c3v, c3v);
                sS[r0r * RP + j]     = n0v;
                sS[r0r * RP + j + 1] = n1v;
                sS[r1r * RP + j]     = n2v;
                sS[r1r * RP + j + 1] = n3v;
                if (outb) {
                    *(float2*)&outb[r0r * 64 + j] = make_float2(n0v, n1v);
                    *(float2*)&outb[r1r * 64 + j] = make_float2(n2v, n3v);
                }
            }
        }
        __syncthreads();
    }

    if (layer == 1) {
#pragma unroll
        for (int q = 0; q < 4; q++) {
            int flat = tid + q * 256;
            int row = flat >> 4, c = (flat & 15) << 2;
            *(float4*)&g_s2[(size_t)(row0 + row) * 64 + c] = *(const float4*)&sS[row * RP + c];
        }
    }
}

// ---------------- FC_out ----------------
__global__ __launch_bounds__(256) void k_fc_out(
        const float* __restrict__ W1, const float* __restrict__ b1,
        const float* __restrict__ W2, const float* __restrict__ b2,
        float* __restrict__ out) {
    __shared__ float sW1[64 * 64];
    __shared__ float sHin[64 * 64];
    __shared__ float sH[64 * 65];
    __shared__ float sW2[64 * 12];
    __shared__ float sb1v[64], sb2v[12];
    int tid = threadIdx.x;
    for (int i = tid; i < 4096; i += 256) sW1[i] = W1[i];
    for (int i = tid; i < 768; i += 256) sW2[i] = W2[i];
    if (tid < 64) sb1v[tid] = b1[tid];
    if (tid < 12) sb2v[tid] = b2[tid];
    int row0 = blockIdx.x * 64;
    for (int i4 = tid; i4 < 1024; i4 += 256) {
        int i = i4 >> 4, c = (i4 & 15) << 2;
        *(float4*)&sHin[i * 64 + c] = *(const float4*)&g_s2[(size_t)(row0 + i) * 64 + c];
    }
    __syncthreads();
    int lane = tid & 31, w = tid >> 5, c0 = lane * 2;
    float acc[8][2];
#pragma unroll
    for (int ri = 0; ri < 8; ri++) { acc[ri][0] = 0.f; acc[ri][1] = 0.f; }
#pragma unroll 8
    for (int k = 0; k < 64; k++) {
        float2 wv = *(const float2*)&sW1[k * 64 + c0];
#pragma unroll
        for (int ri = 0; ri < 8; ri++) {
            float h = sHin[(w + ri * 8) * 64 + k];
            acc[ri][0] = fmaf(h, wv.x, acc[ri][0]);
            acc[ri][1] = fmaf(h, wv.y, acc[ri][1]);
        }
    }
#pragma unroll
    for (int ri = 0; ri < 8; ri++) {
        int i = w + ri * 8;
        sH[i * 65 + c0]     = fmaxf(acc[ri][0] + sb1v[c0], 0.f);
        sH[i * 65 + c0 + 1] = fmaxf(acc[ri][1] + sb1v[c0 + 1], 0.f);
    }
    __syncthreads();
    int i = tid >> 2; int q0 = (tid & 3) * 3;
    float a0 = sb2v[q0], a1 = sb2v[q0 + 1], a2 = sb2v[q0 + 2];
#pragma unroll 8
    for (int k = 0; k < 64; k++) {
        float h = sH[i * 65 + k];
        a0 = fmaf(h, sW2[k * 12 + q0],     a0);
        a1 = fmaf(h, sW2[k * 12 + q0 + 1], a1);
        a2 = fmaf(h, sW2[k * 12 + q0 + 2], a2);
    }
    int r = row0 + i, b = r >> 10, n = r & 1023;
    out[(((size_t)b * Qk + q0)     << 10) + n] = a0;
    out[(((size_t)b * Qk + q0 + 1) << 10) + n] = a1;
    out[(((size_t)b * Qk + q0 + 2) << 10) + n] = a2;
}

// ---------------- launch ----------------
extern "C" void kernel_launch(void* const* d_in, const int* in_sizes, int n_in,
                              void* d_out, int out_size) {
    const float* X     = (const float*)d_in[0];
    const float* SE    = (const float*)d_in[3];
    const float* W_se1 = (const float*)d_in[4];  const float* b_se1 = (const float*)d_in[5];
    const float* W_se2 = (const float*)d_in[6];  const float* b_se2 = (const float*)d_in[7];
    const float* W_te1 = (const float*)d_in[8];  const float* b_te1 = (const float*)d_in[9];
    const float* W_te2 = (const float*)d_in[10]; const float* b_te2 = (const float*)d_in[11];
    const float* W_in1 = (const float*)d_in[12]; const float* b_in1 = (const float*)d_in[13];
    const float* W_in2 = (const float*)d_in[14]; const float* b_in2 = (const float*)d_in[15];
    const float* Wg1   = (const float*)d_in[16]; const float* bg1   = (const float*)d_in[17];
    const float* Wc1   = (const float*)d_in[18]; const float* bc1   = (const float*)d_in[19];
    const float* Wg2   = (const float*)d_in[20]; const float* bg2   = (const float*)d_in[21];
    const float* Wc2   = (const float*)d_in[22]; const float* bc2   = (const float*)d_in[23];
    const float* W_o1  = (const float*)d_in[24]; const float* b_o1  = (const float*)d_in[25];
    const float* W_o2  = (const float*)d_in[26]; const float* b_o2  = (const float*)d_in[27];
    const int*   TE    = (const int*)d_in[28];
    float* out = (float*)d_out;

    const size_t layer_smem = (size_t)42176 * 4;   // 168,704 B
    cudaFuncSetAttribute(k_layer, cudaFuncAttributeMaxDynamicSharedMemorySize,
                         (int)layer_smem);

    k_prep<<<64, 256>>>(Wg1, Wc1, Wg2, Wc2);
    k_se<<<Nk, 64>>>(SE, W_se1, b_se1, W_se2, b_se2);
    k_te<<<Bk * Pk, 64>>>(TE, W_te1, b_te1, W_te2, b_te2);
    k_fc_in<<<Bk * Pk * Nk / 64, 256>>>(X, W_in1, b_in1, W_in2, b_in2);

    k_layer<<<Bk * Nk / 64, 256, layer_smem>>>(0, bg1, bc1);
    k_layer<<<Bk * Nk / 64, 256, layer_smem>>>(1, bg2, bc2);

    k_fc_out<<<Bk * Nk / 64, 256>>>(W_o1, b_o1, W_o2, b_o2, out);
}

// round 7
// speedup vs baseline: 4.7794x; 1.1795x over previous
#include <cuda_runtime.h>

#define Bk 64
#define Pk 12
#define Qk 12
#define Nk 1024
#define Dk 64
#define RP 68          // padded row stride for exact-state smem
#define TS 132         // padded frag-tile stride (floats)
#define XBUF 4224      // 4 mtiles * 8 ktiles * TS

typedef unsigned int uint32;

__device__ __forceinline__ uint32 tf32c(float f) {
    uint32 u;
    asm("cvt.rna.tf32.f32 %0, %1;" : "=r"(u) : "f"(f));
    return u;
}
__device__ __forceinline__ float tf32f(float f) {
    return __uint_as_float(tf32c(f));
}
__device__ __forceinline__ void mma_tf32(float* d, const uint32* a, uint32 b0, uint32 b1) {
    asm("mma.sync.aligned.m16n8k8.row.col.f32.tf32.tf32.f32 "
        "{%0,%1,%2,%3},{%4,%5,%6,%7},{%8,%9},{%0,%1,%2,%3};"
        : "+f"(d[0]), "+f"(d[1]), "+f"(d[2]), "+f"(d[3])
        : "r"(a[0]), "r"(a[1]), "r"(a[2]), "r"(a[3]), "r"(b0), "r"(b1));
}
__device__ __forceinline__ float tanh_a(float z) {
    float y;
    asm("tanh.approx.f32 %0, %1;" : "=f"(y) : "f"(z));
    return y;
}
__device__ __forceinline__ float sigm_a(float z) {      // sigmoid via tanh.approx
    return fmaf(0.5f, tanh_a(0.5f * z), 0.5f);
}
__device__ __forceinline__ float tanh_fast(float z) {   // exact-ish tanh for candidate
    z = fminf(fmaxf(z, -15.f), 15.f);
    float e = __expf(-2.f * z);
    return __fdividef(1.f - e, 1.f + e);
}
// frag-layout offset within a (mtile, ktile) tile for value at (row g | hi*8, col cc)
__device__ __forceinline__ int frag_off(int g, int hi, int cc) {
    return (g * 4 + (cc & 3)) * 4 + hi + ((cc >> 2) << 1);
}

// ---------------- scratch ----------------
__device__ float g_se[Nk * Dk];
__device__ float g_te[Bk * Pk * Dk];
__device__ float g_Xe[(size_t)Bk * Pk * Nk * Dk];
__device__ float g_seq1[(size_t)Bk * Pk * Nk * Dk];
__device__ float g_s2[Bk * Nk * Dk];

// mma B-frag packed, tf32, support-folded.
// gates: [layer][ (part*16+ntile)*4+ktp ][lane*4 + (2*kt2+j)]
__device__ float g_gW[2][16384];
__device__ float g_cW[2][8192];
// fc_in piecewise-linear closed form
__device__ float g_alpha[65 * 64];
__device__ float g_beta[65 * 64];
__device__ float g_ts[64];

// ---------------- weight folding + frag packing ----------------
__global__ void k_prep(const float* __restrict__ Wg1, const float* __restrict__ Wc1,
                       const float* __restrict__ Wg2, const float* __restrict__ Wc2) {
    int tid = blockIdx.x * blockDim.x + threadIdx.x;
    int stride = gridDim.x * blockDim.x;
    for (int i = tid; i < 32768; i += stride) {       // gates
        int v = i & 3, lane = (i >> 2) & 31, ktp = (i >> 7) & 3;
        int n16 = (i >> 9) & 15, p = (i >> 13) & 1, l = (i >> 14) & 1;
        int g = lane >> 2, tig = lane & 3;
        int kt = 2 * ktp + (v >> 1), j = v & 1;
        int k = kt * 8 + tig + 4 * j;
        int n = n16 * 8 + g;
        const float* W = l ? Wg2 : Wg1;
        int r0 = p ? 64 : 0;
        float val = W[(r0 + k) * 128 + n] + W[(r0 + 128 + k) * 128 + n];
        g_gW[l][((p * 16 + n16) * 4 + ktp) * 128 + lane * 4 + v] = tf32f(val);
    }
    for (int i = tid; i < 16384; i += stride) {       // candidate
        int v = i & 3, lane = (i >> 2) & 31, ktp = (i >> 7) & 3;
        int n8 = (i >> 9) & 7, p = (i >> 12) & 1, l = (i >> 13) & 1;
        int g = lane >> 2, tig = lane & 3;
        int kt = 2 * ktp + (v >> 1), j = v & 1;
        int k = kt * 8 + tig + 4 * j;
        int n = n8 * 8 + g;
        const float* W = l ? Wc2 : Wc1;
        int r0 = p ? 64 : 0;
        float val = W[(r0 + k) * 64 + n] + W[(r0 + 128 + k) * 64 + n];
        g_cW[l][((p * 8 + n8) * 4 + ktp) * 128 + lane * 4 + v] = tf32f(val);
    }
}

// ---------------- fc_in piecewise-linear precompute (1 block) ----------------
__global__ void k_prep_seg(const float* __restrict__ W1, const float* __restrict__ b1,
                           const float* __restrict__ W2, const float* __restrict__ b2) {
    __shared__ float w1s[64], b1s[64], tsr[64];
    __shared__ int rnk[64];
    int tid = threadIdx.x;
    if (tid < 64) { w1s[tid] = W1[tid]; b1s[tid] = b1[tid]; }
    __syncthreads();
    if (tid < 64) {
        float w = w1s[tid];
        float t = (w != 0.f) ? (-b1s[tid] / w) : __int_as_float(0x7f800000);
        tsr[tid] = t;
    }
    __syncthreads();
    if (tid < 64) {
        float t = tsr[tid];
        int r = 0;
        for (int d = 0; d < 64; d++) {
            float td = tsr[d];
            r += (td < t) || (td == t && d < tid);
        }
        rnk[tid] = r;
        g_ts[r] = t;
    }
    __syncthreads();
    for (int idx = tid; idx < 65 * 64; idx += blockDim.x) {
        int s = idx >> 6, c = idx & 63;
        float a = 0.f, bt = 0.f;
        for (int d = 0; d < 64; d++) {
            float w = w1s[d];
            bool act = (w > 0.f) ? (rnk[d] < s)
                     : ((w < 0.f) ? (rnk[d] >= s) : (b1s[d] > 0.f));
            if (act) {
                float w2 = W2[d * 64 + c];
                a = fmaf(w, w2, a);
                bt = fmaf(b1s[d], w2, bt);
            }
        }
        g_alpha[idx] = a;
        g_beta[idx] = bt + b2[c];
    }
}

// ---------------- spatial embedding ----------------
__global__ void k_se(const float* __restrict__ SE, const float* __restrict__ W1,
                     const float* __restrict__ b1, const float* __restrict__ W2,
                     const float* __restrict__ b2) {
    __shared__ float xs[64], hs[64];
    int n = blockIdx.x, d = threadIdx.x;
    xs[d] = SE[n * 64 + d];
    __syncthreads();
    float a = b1[d];
#pragma unroll 8
    for (int k = 0; k < 64; k++) a = fmaf(xs[k], W1[k * 64 + d], a);
    hs[d] = fmaxf(a, 0.f);
    __syncthreads();
    float o = b2[d];
#pragma unroll 8
    for (int k = 0; k < 64; k++) o = fmaf(hs[k], W2[k * 64 + d], o);
    g_se[n * 64 + d] = o;
}

// ---------------- temporal embedding ----------------
__global__ void k_te(const int* __restrict__ TE, const float* __restrict__ W1,
                     const float* __restrict__ b1, const float* __restrict__ W2,
                     const float* __restrict__ b2) {
    __shared__ float hs[64];
    int row = blockIdx.x;
    int b = row / Pk, p = row - b * Pk;
    int d = threadIdx.x;
    int base = (b * (Pk + Qk) + p) * 2;
    int t0 = TE[base], t1 = TE[base + 1];
    float a = W1[t0 * 64 + d] + W1[(7 + t1) * 64 + d] + b1[d];
    hs[d] = fmaxf(a, 0.f);
    __syncthreads();
    float o = b2[d];
#pragma unroll 8
    for (int k = 0; k < 64; k++) o = fmaf(hs[k], W2[k * 64 + d], o);
    g_te[row * 64 + d] = o;
}

// ---------------- FC_in: closed-form per-row affine ----------------
__global__ __launch_bounds__(256) void k_fc_in_fast(const float* __restrict__ X) {
    __shared__ float sA[65 * 64], sB[65 * 64], sTs[64], sXs[384];
    __shared__ int sSeg[384];
    int tid = threadIdx.x;
    {
        const float4* a = (const float4*)g_alpha;
        const float4* b = (const float4*)g_beta;
        float4* da = (float4*)sA;
        float4* db = (float4*)sB;
        for (int i = tid; i < 1040; i += 256) { da[i] = a[i]; db[i] = b[i]; }
    }
    if (tid < 64) sTs[tid] = g_ts[tid];
    int row0 = blockIdx.x * 384;
    __syncthreads();
    for (int i = tid; i < 384; i += 256) {
        float x = X[row0 + i];
        sXs[i] = x;
        int sg = 0;
#pragma unroll 16
        for (int k = 0; k < 64; k++) sg += (sTs[k] < x);
        sSeg[i] = sg;
    }
    __syncthreads();
#pragma unroll 4
    for (int it = 0; it < 24; it++) {
        int flat = it * 256 + tid;
        int lr = flat >> 4, c4 = (flat & 15) << 2;
        float x = sXs[lr];
        int sg = sSeg[lr];
        float4 a = *(const float4*)&sA[sg * 64 + c4];
        float4 bt = *(const float4*)&sB[sg * 64 + c4];
        int r = row0 + lr, n = r & (Nk - 1), bp = r >> 10;
        float4 se4 = *(const float4*)&g_se[n * 64 + c4];
        float4 te4 = *(const float4*)&g_te[bp * 64 + c4];
        float4 o;
        o.x = fmaf(x, a.x, bt.x) + se4.x + te4.x;
        o.y = fmaf(x, a.y, bt.y) + se4.y + te4.y;
        o.z = fmaf(x, a.z, bt.z) + se4.z + te4.z;
        o.w = fmaf(x, a.w, bt.w) + se4.w + te4.w;
        *(float4*)&g_Xe[(size_t)r * 64 + c4] = o;
    }
}

// ---------------- persistent DCGRU layer: frag-layout tf32 scan ----------------
// smem floats: gWf 16384 | cWf 8192 | sbg 128 | sbc 64 | sXf 2*4224 | sSf 4224 | sRf 4224 | sSe 4352
__global__ __launch_bounds__(256, 1) void k_layer(int layer,
        const float* __restrict__ bg, const float* __restrict__ bc) {
    extern __shared__ float sm[];
    float* gWf = sm;
    float* cWf = sm + 16384;
    float* sbg = sm + 24576;
    float* sbc = sm + 24704;
    float* sXf = sm + 24768;
    float* sSf = sm + 33216;
    float* sRf = sm + 37440;
    float* sSe = sm + 41664;

    int tid = threadIdx.x;
    {
        const float4* a = (const float4*)g_gW[layer];
        float4* d = (float4*)gWf;
        for (int i = tid; i < 4096; i += 256) d[i] = a[i];
        const float4* c = (const float4*)g_cW[layer];
        float4* dc = (float4*)cWf;
        for (int i = tid; i < 2048; i += 256) dc[i] = c[i];
    }
    if (tid < 128) sbg[tid] = bg[tid];
    if (tid < 64)  sbc[tid] = bc[tid];
    for (int i = tid; i < 4224; i += 256) sSf[i] = 0.f;
    for (int i = tid; i < 4352; i += 256) sSe[i] = 0.f;

    int row0 = blockIdx.x * 64;
    int b = row0 >> 10, n0 = row0 & (Nk - 1);
    const float* Xbase = (layer == 0) ? g_Xe : g_seq1;

    // install x(0) into buffer 0 (tf32, frag layout)
    {
        const float4* x0 = (const float4*)&Xbase[((size_t)(b * Pk) * Nk + n0) * 64];
#pragma unroll
        for (int q = 0; q < 4; q++) {
            int flat = tid + q * 256;
            float4 v = x0[flat];
            int row = flat >> 4, c0 = (flat & 15) << 2;
            int mt = row >> 4, lr = row & 15, g = lr & 7, hi = lr >> 3;
            int kt = c0 >> 3, ccb = c0 & 7;
            float* fb = &sXf[(mt * 8 + kt) * TS];
            fb[frag_off(g, hi, ccb + 0)] = tf32f(v.x);
            fb[frag_off(g, hi, ccb + 1)] = tf32f(v.y);
            fb[frag_off(g, hi, ccb + 2)] = tf32f(v.z);
            fb[frag_off(g, hi, ccb + 3)] = tf32f(v.w);
        }
    }
    __syncthreads();

    int lane = tid & 31, w = tid >> 5;
    int g = lane >> 2, tig = lane & 3, tig2 = 2 * tig;
    int mp = w & 1, nq = w >> 1;

    float bgr[2][2], bgu[2][2], bcv[2][2];
#pragma unroll
    for (int nt = 0; nt < 2; nt++) {
        int j = 16 * nq + 8 * nt + tig2;
        bgr[nt][0] = sbg[j];      bgr[nt][1] = sbg[j + 1];
        bgu[nt][0] = sbg[64 + j]; bgu[nt][1] = sbg[64 + j + 1];
        bcv[nt][0] = sbc[j];      bcv[nt][1] = sbc[j + 1];
    }

    for (int t = 0; t < Pk; t++) {
        int cur = t & 1;
        float* Xc = sXf + cur * XBUF;
        float4 pre[4];
        if (t + 1 < Pk) {
            const float4* xs = (const float4*)&Xbase[((size_t)(b * Pk + t + 1) * Nk + n0) * 64];
#pragma unroll
            for (int q = 0; q < 4; q++) pre[q] = xs[tid + q * 256];
        }

        // ---- phase A: gates ----
        float accR[2][2][4], accU[2][2][4];
#pragma unroll
        for (int mt = 0; mt < 2; mt++)
#pragma unroll
            for (int nt = 0; nt < 2; nt++)
#pragma unroll
                for (int v = 0; v < 4; v++) { accR[mt][nt][v] = 0.f; accU[mt][nt][v] = 0.f; }

#pragma unroll
        for (int ktp = 0; ktp < 4; ktp++) {
            float4 bRx[2], bRs[2], bUx[2], bUs[2];
#pragma unroll
            for (int nt = 0; nt < 2; nt++) {
                int nr = 2 * nq + nt, nu = 8 + 2 * nq + nt;
                bRx[nt] = *(const float4*)&gWf[(nr * 4 + ktp) * 128 + lane * 4];
                bRs[nt] = *(const float4*)&gWf[((16 + nr) * 4 + ktp) * 128 + lane * 4];
                bUx[nt] = *(const float4*)&gWf[(nu * 4 + ktp) * 128 + lane * 4];
                bUs[nt] = *(const float4*)&gWf[((16 + nu) * 4 + ktp) * 128 + lane * 4];
            }
#pragma unroll
            for (int k2 = 0; k2 < 2; k2++) {
                int kt = ktp * 2 + k2;
                uint32 ax[2][4], as2[2][4];
#pragma unroll
                for (int mt = 0; mt < 2; mt++) {
                    int off = ((2 * mp + mt) * 8 + kt) * TS + lane * 4;
                    float4 xv = *(const float4*)&Xc[off];
                    float4 sv = *(const float4*)&sSf[off];
                    ax[mt][0] = __float_as_uint(xv.x); ax[mt][1] = __float_as_uint(xv.y);
                    ax[mt][2] = __float_as_uint(xv.z); ax[mt][3] = __float_as_uint(xv.w);
                    as2[mt][0] = __float_as_uint(sv.x); as2[mt][1] = __float_as_uint(sv.y);
                    as2[mt][2] = __float_as_uint(sv.z); as2[mt][3] = __float_as_uint(sv.w);
                }
#pragma unroll
                for (int nt = 0; nt < 2; nt++) {
                    uint32 rx0 = __float_as_uint(k2 ? bRx[nt].z : bRx[nt].x);
                    uint32 rx1 = __float_as_uint(k2 ? bRx[nt].w : bRx[nt].y);
                    uint32 rs0 = __float_as_uint(k2 ? bRs[nt].z : bRs[nt].x);
                    uint32 rs1 = __float_as_uint(k2 ? bRs[nt].w : bRs[nt].y);
                    uint32 ux0 = __float_as_uint(k2 ? bUx[nt].z : bUx[nt].x);
                    uint32 ux1 = __float_as_uint(k2 ? bUx[nt].w : bUx[nt].y);
                    uint32 us0 = __float_as_uint(k2 ? bUs[nt].z : bUs[nt].x);
                    uint32 us1 = __float_as_uint(k2 ? bUs[nt].w : bUs[nt].y);
#pragma unroll
                    for (int mt = 0; mt < 2; mt++) {
                        mma_tf32(accR[mt][nt], ax[mt], rx0, rx1);
                        mma_tf32(accR[mt][nt], as2[mt], rs0, rs1);
                        mma_tf32(accU[mt][nt], ax[mt], ux0, ux1);
                        mma_tf32(accU[mt][nt], as2[mt], us0, us1);
                    }
                }
            }
        }

        // ---- epilogue A: r,u sigmoids; r*s (tf32) scattered to sRf; u stays in regs ----
        float uval[2][2][4];
#pragma unroll
        for (int mt = 0; mt < 2; mt++) {
            int mtg = 2 * mp + mt;
            int r0 = mtg * 16 + g, r1 = r0 + 8;
#pragma unroll
            for (int nt = 0; nt < 2; nt++) {
                int j = 16 * nq + 8 * nt + tig2;
                float rv0 = sigm_a(accR[mt][nt][0] + bgr[nt][0]);
                float rv1 = sigm_a(accR[mt][nt][1] + bgr[nt][1]);
                float rv2 = sigm_a(accR[mt][nt][2] + bgr[nt][0]);
                float rv3 = sigm_a(accR[mt][nt][3] + bgr[nt][1]);
                uval[mt][nt][0] = sigm_a(accU[mt][nt][0] + bgu[nt][0]);
                uval[mt][nt][1] = sigm_a(accU[mt][nt][1] + bgu[nt][1]);
                uval[mt][nt][2] = sigm_a(accU[mt][nt][2] + bgu[nt][0]);
                uval[mt][nt][3] = sigm_a(accU[mt][nt][3] + bgu[nt][1]);
                float2 s01 = *(const float2*)&sSe[r0 * RP + j];
                float2 s23 = *(const float2*)&sSe[r1 * RP + j];
                int kt = 2 * nq + nt;
                float* fb = &sRf[(mtg * 8 + kt) * TS];
                fb[frag_off(g, 0, tig2)]     = tf32f(rv0 * s01.x);
                fb[frag_off(g, 0, tig2 + 1)] = tf32f(rv1 * s01.y);
                fb[frag_off(g, 1, tig2)]     = tf32f(rv2 * s23.x);
                fb[frag_off(g, 1, tig2 + 1)] = tf32f(rv3 * s23.y);
            }
        }
        __syncthreads();

        // ---- phase B: candidate ----
        float accB[2][2][4];
#pragma unroll
        for (int mt = 0; mt < 2; mt++)
#pragma unroll
            for (int nt = 0; nt < 2; nt++)
#pragma unroll
                for (int v = 0; v < 4; v++) accB[mt][nt][v] = 0.f;

#pragma unroll
        for (int ktp = 0; ktp < 4; ktp++) {
            float4 bx[2], bs[2];
#pragma unroll
            for (int nt = 0; nt < 2; nt++) {
                int nc = 2 * nq + nt;
                bx[nt] = *(const float4*)&cWf[(nc * 4 + ktp) * 128 + lane * 4];
                bs[nt] = *(const float4*)&cWf[((8 + nc) * 4 + ktp) * 128 + lane * 4];
            }
#pragma unroll
            for (int k2 = 0; k2 < 2; k2++) {
                int kt = ktp * 2 + k2;
                uint32 ax[2][4], ar[2][4];
#pragma unroll
                for (int mt = 0; mt < 2; mt++) {
                    int off = ((2 * mp + mt) * 8 + kt) * TS + lane * 4;
                    float4 xv = *(const float4*)&Xc[off];
                    float4 rv = *(const float4*)&sRf[off];
                    ax[mt][0] = __float_as_uint(xv.x); ax[mt][1] = __float_as_uint(xv.y);
                    ax[mt][2] = __float_as_uint(xv.z); ax[mt][3] = __float_as_uint(xv.w);
                    ar[mt][0] = __float_as_uint(rv.x); ar[mt][1] = __float_as_uint(rv.y);
                    ar[mt][2] = __float_as_uint(rv.z); ar[mt][3] = __float_as_uint(rv.w);
                }
#pragma unroll
                for (int nt = 0; nt < 2; nt++) {
                    uint32 x0 = __float_as_uint(k2 ? bx[nt].z : bx[nt].x);
                    uint32 x1 = __float_as_uint(k2 ? bx[nt].w : bx[nt].y);
                    uint32 s0 = __float_as_uint(k2 ? bs[nt].z : bs[nt].x);
                    uint32 s1 = __float_as_uint(k2 ? bs[nt].w : bs[nt].y);
#pragma unroll
                    for (int mt = 0; mt < 2; mt++) {
                        mma_tf32(accB[mt][nt], ax[mt], x0, x1);
                        mma_tf32(accB[mt][nt], ar[mt], s0, s1);
                    }
                }
            }
        }

        // install prefetched x(t+1) into alternate buffer
        if (t + 1 < Pk) {
            float* Xn = sXf + (cur ^ 1) * XBUF;
#pragma unroll
            for (int q = 0; q < 4; q++) {
                int flat = tid + q * 256;
                float4 v = pre[q];
                int row = flat >> 4, c0 = (flat & 15) << 2;
                int mt = row >> 4, lr = row & 15, gg = lr & 7, hi = lr >> 3;
                int kt = c0 >> 3, ccb = c0 & 7;
                float* fb = &Xn[(mt * 8 + kt) * TS];
                fb[frag_off(gg, hi, ccb + 0)] = tf32f(v.x);
                fb[frag_off(gg, hi, ccb + 1)] = tf32f(v.y);
                fb[frag_off(gg, hi, ccb + 2)] = tf32f(v.z);
                fb[frag_off(gg, hi, ccb + 3)] = tf32f(v.w);
            }
        }

        // ---- epilogue B: c = tanh, new = u*s + (1-u)*c ----
        float* outb = (layer == 0)
            ? &g_seq1[((size_t)(b * Pk + t) * Nk + n0) * 64] : (float*)0;
#pragma unroll
        for (int mt = 0; mt < 2; mt++) {
            int mtg = 2 * mp + mt;
            int r0 = mtg * 16 + g, r1 = r0 + 8;
#pragma unroll
            for (int nt = 0; nt < 2; nt++) {
                int j = 16 * nq + 8 * nt + tig2;
                float c0v = tanh_fast(accB[mt][nt][0] + bcv[nt][0]);
                float c1v = tanh_fast(accB[mt][nt][1] + bcv[nt][1]);
                float c2v = tanh_fast(accB[mt][nt][2] + bcv[nt][0]);
                float c3v = tanh_fast(accB[mt][nt][3] + bcv[nt][1]);
                float2 s01 = *(const float2*)&sSe[r0 * RP + j];
                float2 s23 = *(const float2*)&sSe[r1 * RP + j];
                float n0v = fmaf(uval[mt][nt][0], s01.x - c0v, c0v);
                float n1v = fmaf(uval[mt][nt][1], s01.y - c1v, c1v);
                float n2v = fmaf(uval[mt][nt][2], s23.x - c2v, c2v);
                float n3v = fmaf(uval[mt][nt][3], s23.y - c3v, c3v);
                *(float2*)&sSe[r0 * RP + j] = make_float2(n0v, n1v);
                *(float2*)&sSe[r1 * RP + j] = make_float2(n2v, n3v);
                int kt = 2 * nq + nt;
                float* fb = &sSf[(mtg * 8 + kt) * TS];
                fb[frag_off(g, 0, tig2)]     = tf32f(n0v);
                fb[frag_off(g, 0, tig2 + 1)] = tf32f(n1v);
                fb[frag_off(g, 1, tig2)]     = tf32f(n2v);
                fb[frag_off(g, 1, tig2 + 1)] = tf32f(n3v);
                if (outb) {
                    *(float2*)&outb[r0 * 64 + j] = make_float2(n0v, n1v);
                    *(float2*)&outb[r1 * 64 + j] = make_float2(n2v, n3v);
                }
            }
        }
        __syncthreads();
    }

    if (layer == 1) {
#pragma unroll
        for (int q = 0; q < 4; q++) {
            int flat = tid + q * 256;
            int row = flat >> 4, c = (flat & 15) << 2;
            *(float4*)&g_s2[(size_t)(row0 + row) * 64 + c] = *(const float4*)&sSe[row * RP + c];
        }
    }
}

// ---------------- FC_out ----------------
__global__ __launch_bounds__(256) void k_fc_out(
        const float* __restrict__ W1, const float* __restrict__ b1,
        const float* __restrict__ W2, const float* __restrict__ b2,
        float* __restrict__ out) {
    __shared__ float sW1[64 * 64];
    __shared__ float sHin[64 * 64];
    __shared__ float sH[64 * 65];
    __shared__ float sW2[64 * 12];
    __shared__ float sb1v[64], sb2v[12];
    int tid = threadIdx.x;
    for (int i = tid; i < 4096; i += 256) sW1[i] = W1[i];
    for (int i = tid; i < 768; i += 256) sW2[i] = W2[i];
    if (tid < 64) sb1v[tid] = b1[tid];
    if (tid < 12) sb2v[tid] = b2[tid];
    int row0 = blockIdx.x * 64;
    for (int i4 = tid; i4 < 1024; i4 += 256) {
        int i = i4 >> 4, c = (i4 & 15) << 2;
        *(float4*)&sHin[i * 64 + c] = *(const float4*)&g_s2[(size_t)(row0 + i) * 64 + c];
    }
    __syncthreads();
    int lane = tid & 31, w = tid >> 5, c0 = lane * 2;
    float acc[8][2];
#pragma unroll
    for (int ri = 0; ri < 8; ri++) { acc[ri][0] = 0.f; acc[ri][1] = 0.f; }
#pragma unroll 8
    for (int k = 0; k < 64; k++) {
        float2 wv = *(const float2*)&sW1[k * 64 + c0];
#pragma unroll
        for (int ri = 0; ri < 8; ri++) {
            float h = sHin[(w + ri * 8) * 64 + k];
            acc[ri][0] = fmaf(h, wv.x, acc[ri][0]);
            acc[ri][1] = fmaf(h, wv.y, acc[ri][1]);
        }
    }
#pragma unroll
    for (int ri = 0; ri < 8; ri++) {
        int i = w + ri * 8;
        sH[i * 65 + c0]     = fmaxf(acc[ri][0] + sb1v[c0], 0.f);
        sH[i * 65 + c0 + 1] = fmaxf(acc[ri][1] + sb1v[c0 + 1], 0.f);
    }
    __syncthreads();
    int i = tid >> 2;
    int q0 = (tid & 3) * 3;
    float a0 = sb2v[q0], a1 = sb2v[q0 + 1], a2 = sb2v[q0 + 2];
#pragma unroll 8
    for (int k = 0; k < 64; k++) {
        float h = sH[i * 65 + k];
        a0 = fmaf(h, sW2[k * 12 + q0],     a0);
        a1 = fmaf(h, sW2[k * 12 + q0 + 1], a1);
        a2 = fmaf(h, sW2[k * 12 + q0 + 2], a2);
    }
    int r = row0 + i, b = r >> 10, n = r & 1023;
    out[(((size_t)b * Qk + q0)     << 10) + n] = a0;
    out[(((size_t)b * Qk + q0 + 1) << 10) + n] = a1;
    out[(((size_t)b * Qk + q0 + 2) << 10) + n] = a2;
}

// ---------------- launch ----------------
extern "C" void kernel_launch(void* const* d_in, const int* in_sizes, int n_in,
                              void* d_out, int out_size) {
    const float* X     = (const float*)d_in[0];
    const float* SE    = (const float*)d_in[3];
    const float* W_se1 = (const float*)d_in[4];  const float* b_se1 = (const float*)d_in[5];
    const float* W_se2 = (const float*)d_in[6];  const float* b_se2 = (const float*)d_in[7];
    const float* W_te1 = (const float*)d_in[8];  const float* b_te1 = (const float*)d_in[9];
    const float* W_te2 = (const float*)d_in[10]; const float* b_te2 = (const float*)d_in[11];
    const float* W_in1 = (const float*)d_in[12]; const float* b_in1 = (const float*)d_in[13];
    const float* W_in2 = (const float*)d_in[14]; const float* b_in2 = (const float*)d_in[15];
    const float* Wg1   = (const float*)d_in[16]; const float* bg1   = (const float*)d_in[17];
    const float* Wc1   = (const float*)d_in[18]; const float* bc1   = (const float*)d_in[19];
    const float* Wg2   = (const float*)d_in[20]; const float* bg2   = (const float*)d_in[21];
    const float* Wc2   = (const float*)d_in[22]; const float* bc2   = (const float*)d_in[23];
    const float* W_o1  = (const float*)d_in[24]; const float* b_o1  = (const float*)d_in[25];
    const float* W_o2  = (const float*)d_in[26]; const float* b_o2  = (const float*)d_in[27];
    const int*   TE    = (const int*)d_in[28];
    float* out = (float*)d_out;

    const size_t layer_smem = (size_t)46016 * 4;   // 184,064 B
    cudaFuncSetAttribute(k_layer, cudaFuncAttributeMaxDynamicSharedMemorySize,
                         (int)layer_smem);

    k_prep<<<64, 256>>>(Wg1, Wc1, Wg2, Wc2);
    k_prep_seg<<<1, 256>>>(W_in1, b_in1, W_in2, b_in2);
    k_se<<<Nk, 64>>>(SE, W_se1, b_se1, W_se2, b_se2);
    k_te<<<Bk * Pk, 64>>>(TE, W_te1, b_te1, W_te2, b_te2);
    k_fc_in_fast<<<2048, 256>>>(X);

    k_layer<<<Bk * Nk / 64, 256, layer_smem>>>(0, bg1, bc1);
    k_layer<<<Bk * Nk / 64, 256, layer_smem>>>(1, bg2, bc2);

    k_fc_out<<<Bk * Nk / 64, 256>>>(W_o1, b_o1, W_o2, b_o2, out);
}

// round 8
// speedup vs baseline: 7.5673x; 1.5833x over previous
#include <cuda_runtime.h>
#include <cuda_fp16.h>

#define Bk 64
#define Pk 12
#define Qk 12
#define Nk 1024
#define Dk 64

typedef unsigned int uint32;

__device__ __forceinline__ uint32 packh2(float a, float b) {
    __half2 h = __floats2half2_rn(a, b);
    return *(uint32*)&h;
}
__device__ __forceinline__ void mma_f16(float* d, uint4 a, uint32 b0, uint32 b1) {
    asm("mma.sync.aligned.m16n8k16.row.col.f32.f16.f16.f32 "
        "{%0,%1,%2,%3},{%4,%5,%6,%7},{%8,%9},{%0,%1,%2,%3};"
        : "+f"(d[0]), "+f"(d[1]), "+f"(d[2]), "+f"(d[3])
        : "r"(a.x), "r"(a.y), "r"(a.z), "r"(a.w), "r"(b0), "r"(b1));
}
__device__ __forceinline__ float tanh_a(float z) {
    float y;
    asm("tanh.approx.f32 %0, %1;" : "=f"(y) : "f"(z));
    return y;
}
__device__ __forceinline__ float sigm_a(float z) {
    return fmaf(0.5f, tanh_a(0.5f * z), 0.5f);
}
__device__ __forceinline__ float tanh_fast(float z) {
    z = fminf(fmaxf(z, -15.f), 15.f);
    float e = __expf(-2.f * z);
    return __fdividef(1.f - e, 1.f + e);
}

// ---------------- scratch ----------------
__device__ float g_se[Nk * Dk];
__device__ float g_te[Bk * Pk * Dk];
__device__ float g_s2[Bk * Nk * Dk];
// fp16 A-frag layout Xe: key = (b*Pk+p)*16 + ntile ; per key 2048 uint32
__device__ uint32 g_XeH[(size_t)Bk * Pk * 16 * 2048];
// fp16 B-frag packed folded weights
__device__ uint32 g_gWh[2][8192];   // gates: ((pt*16+n8)*2+ktp)*128 + lane*4 + v
__device__ uint32 g_cWh[2][4096];   // cand : ((pt*8+n8)*2+ktp)*128 + lane*4 + v
// fc_in piecewise-linear closed form
__device__ float g_alpha[65 * 64];
__device__ float g_beta[65 * 64];
__device__ float g_ts[64];

// ---------------- weight folding + fp16 frag packing ----------------
__global__ void k_prep(const float* __restrict__ Wg1, const float* __restrict__ Wc1,
                       const float* __restrict__ Wg2, const float* __restrict__ Wc2) {
    int tid = blockIdx.x * blockDim.x + threadIdx.x;
    int stride = gridDim.x * blockDim.x;
    // gates: v(2) lane(5) ktp(1) n8(4) pt(1) l(1)
    for (int i = tid; i < 16384; i += stride) {
        int v = i & 3, lane = (i >> 2) & 31, ktp = (i >> 7) & 1;
        int n8 = (i >> 8) & 15, pt = (i >> 12) & 1, l = (i >> 13) & 1;
        int kt = 2 * ktp + (v >> 1), reg = v & 1;
        int g = lane >> 2, tig = lane & 3;
        int k0 = kt * 16 + 2 * tig + 8 * reg;
        int n = n8 * 8 + g;
        const float* W = l ? Wg2 : Wg1;
        int r0 = pt * 64;
        float f0 = W[(r0 + k0) * 128 + n] + W[(r0 + 128 + k0) * 128 + n];
        float f1 = W[(r0 + k0 + 1) * 128 + n] + W[(r0 + 129 + k0) * 128 + n];
        g_gWh[l][((pt * 16 + n8) * 2 + ktp) * 128 + lane * 4 + v] = packh2(f0, f1);
    }
    // cand: v(2) lane(5) ktp(1) n8(3) pt(1) l(1)
    for (int i = tid; i < 8192; i += stride) {
        int v = i & 3, lane = (i >> 2) & 31, ktp = (i >> 7) & 1;
        int n8 = (i >> 8) & 7, pt = (i >> 11) & 1, l = (i >> 12) & 1;
        int kt = 2 * ktp + (v >> 1), reg = v & 1;
        int g = lane >> 2, tig = lane & 3;
        int k0 = kt * 16 + 2 * tig + 8 * reg;
        int n = n8 * 8 + g;
        const float* W = l ? Wc2 : Wc1;
        int r0 = pt * 64;
        float f0 = W[(r0 + k0) * 64 + n] + W[(r0 + 128 + k0) * 64 + n];
        float f1 = W[(r0 + k0 + 1) * 64 + n] + W[(r0 + 129 + k0) * 64 + n];
        g_cWh[l][((pt * 8 + n8) * 2 + ktp) * 128 + lane * 4 + v] = packh2(f0, f1);
    }
}

// ---------------- fc_in piecewise-linear precompute ----------------
__global__ void k_prep_seg(const float* __restrict__ W1, const float* __restrict__ b1,
                           const float* __restrict__ W2, const float* __restrict__ b2) {
    __shared__ float w1s[64], b1s[64], tsr[64];
    __shared__ int rnk[64];
    int tid = threadIdx.x;
    if (tid < 64) { w1s[tid] = W1[tid]; b1s[tid] = b1[tid]; }
    __syncthreads();
    if (tid < 64) {
        float w = w1s[tid];
        tsr[tid] = (w != 0.f) ? (-b1s[tid] / w) : __int_as_float(0x7f800000);
    }
    __syncthreads();
    if (tid < 64) {
        float t = tsr[tid];
        int r = 0;
        for (int d = 0; d < 64; d++) {
            float td = tsr[d];
            r += (td < t) || (td == t && d < tid);
        }
        rnk[tid] = r;
        g_ts[r] = t;
    }
    __syncthreads();
    for (int idx = tid; idx < 65 * 64; idx += blockDim.x) {
        int s = idx >> 6, c = idx & 63;
        float a = 0.f, bt = 0.f;
        for (int d = 0; d < 64; d++) {
            float w = w1s[d];
            bool act = (w > 0.f) ? (rnk[d] < s)
                     : ((w < 0.f) ? (rnk[d] >= s) : (b1s[d] > 0.f));
            if (act) {
                float w2 = W2[d * 64 + c];
                a = fmaf(w, w2, a);
                bt = fmaf(b1s[d], w2, bt);
            }
        }
        g_alpha[idx] = a;
        g_beta[idx] = bt + b2[c];
    }
}

// ---------------- spatial embedding ----------------
__global__ void k_se(const float* __restrict__ SE, const float* __restrict__ W1,
                     const float* __restrict__ b1, const float* __restrict__ W2,
                     const float* __restrict__ b2) {
    __shared__ float xs[64], hs[64];
    int n = blockIdx.x, d = threadIdx.x;
    xs[d] = SE[n * 64 + d];
    __syncthreads();
    float a = b1[d];
#pragma unroll 8
    for (int k = 0; k < 64; k++) a = fmaf(xs[k], W1[k * 64 + d], a);
    hs[d] = fmaxf(a, 0.f);
    __syncthreads();
    float o = b2[d];
#pragma unroll 8
    for (int k = 0; k < 64; k++) o = fmaf(hs[k], W2[k * 64 + d], o);
    g_se[n * 64 + d] = o;
}

// ---------------- temporal embedding ----------------
__global__ void k_te(const int* __restrict__ TE, const float* __restrict__ W1,
                     const float* __restrict__ b1, const float* __restrict__ W2,
                     const float* __restrict__ b2) {
    __shared__ float hs[64];
    int row = blockIdx.x;
    int b = row / Pk, p = row - b * Pk;
    int d = threadIdx.x;
    int base = (b * (Pk + Qk) + p) * 2;
    int t0 = TE[base], t1 = TE[base + 1];
    float a = W1[t0 * 64 + d] + W1[(7 + t1) * 64 + d] + b1[d];
    hs[d] = fmaxf(a, 0.f);
    __syncthreads();
    float o = b2[d];
#pragma unroll 8
    for (int k = 0; k < 64; k++) o = fmaf(hs[k], W2[k * 64 + d], o);
    g_te[row * 64 + d] = o;
}

// ---------------- FC_in: closed-form affine -> fp16 frag output ----------------
__global__ __launch_bounds__(256) void k_fc_in_h(const float* __restrict__ X) {
    __shared__ float sA[65 * 64], sB[65 * 64], sTs[64], sTe[64];
    __shared__ float sXs[1024];
    __shared__ int sSeg[1024];
    int tid = threadIdx.x;
    int bp = blockIdx.x;
    {
        const float4* a = (const float4*)g_alpha;
        const float4* b = (const float4*)g_beta;
        float4* da = (float4*)sA;
        float4* db = (float4*)sB;
        for (int i = tid; i < 1040; i += 256) { da[i] = a[i]; db[i] = b[i]; }
    }
    if (tid < 64) { sTs[tid] = g_ts[tid]; sTe[tid] = g_te[bp * 64 + tid]; }
    __syncthreads();
    for (int i = tid; i < 1024; i += 256) {
        float x = X[(size_t)bp * 1024 + i];
        sXs[i] = x;
        int sg = 0;
#pragma unroll 16
        for (int k = 0; k < 64; k++) sg += (sTs[k] < x);
        sSeg[i] = sg;
    }
    __syncthreads();
#pragma unroll 4
    for (int it = 0; it < 32; it++) {
        int sl = it * 256 + tid;
        int nt = sl >> 9, r9 = sl & 511;
        int mt = r9 >> 7, kt = (r9 >> 5) & 3, s = r9 & 31;
        int g = s >> 2, tig = s & 3;
        int n0 = nt * 64 + 16 * mt + g, n1 = n0 + 8;
        int c0 = 16 * kt + 2 * tig, c1 = c0 + 8;
        float x0 = sXs[n0], x1 = sXs[n1];
        int s0 = sSeg[n0] * 64, s1 = sSeg[n1] * 64;
        float2 a00 = *(const float2*)&sA[s0 + c0], b00 = *(const float2*)&sB[s0 + c0];
        float2 a01 = *(const float2*)&sA[s0 + c1], b01 = *(const float2*)&sB[s0 + c1];
        float2 a10 = *(const float2*)&sA[s1 + c0], b10 = *(const float2*)&sB[s1 + c0];
        float2 a11 = *(const float2*)&sA[s1 + c1], b11 = *(const float2*)&sB[s1 + c1];
        float2 se00 = *(const float2*)&g_se[n0 * 64 + c0];
        float2 se01 = *(const float2*)&g_se[n0 * 64 + c1];
        float2 se10 = *(const float2*)&g_se[n1 * 64 + c0];
        float2 se11 = *(const float2*)&g_se[n1 * 64 + c1];
        float2 te0 = *(const float2*)&sTe[c0];
        float2 te1 = *(const float2*)&sTe[c1];
        uint32 u0 = packh2(fmaf(x0, a00.x, b00.x) + se00.x + te0.x,
                           fmaf(x0, a00.y, b00.y) + se00.y + te0.y);
        uint32 u1 = packh2(fmaf(x1, a10.x, b10.x) + se10.x + te0.x,
                           fmaf(x1, a10.y, b10.y) + se10.y + te0.y);
        uint32 u2 = packh2(fmaf(x0, a01.x, b01.x) + se01.x + te1.x,
                           fmaf(x0, a01.y, b01.y) + se01.y + te1.y);
        uint32 u3 = packh2(fmaf(x1, a11.x, b11.x) + se11.x + te1.x,
                           fmaf(x1, a11.y, b11.y) + se11.y + te1.y);
        *(uint4*)&g_XeH[(size_t)(bp * 16 + nt) * 2048 + (mt * 4 + kt) * 128 + s * 4] =
            make_uint4(u0, u1, u2, u3);
    }
}

// ---------------- one GRU cell (phase A + B) on fp16 frags ----------------
__device__ __forceinline__ void gru_cell(
        const uint32* __restrict__ Xc, uint32* __restrict__ Sf, uint32* __restrict__ Rf,
        const uint32* __restrict__ gWl, const uint32* __restrict__ cWl,
        float (&sr)[2][2][4],
        const float (&bgr)[2][2], const float (&bgu)[2][2], const float (&bcc)[2][2],
        int lane, int mp, int nq, int g, int tig,
        bool inst, uint32* Xn, uint4 pf0, uint4 pf1, int tid) {
    // ---- phase A: gates ----
    float aR[2][2][4], aU[2][2][4];
#pragma unroll
    for (int mt = 0; mt < 2; mt++)
#pragma unroll
        for (int nt = 0; nt < 2; nt++)
#pragma unroll
            for (int v = 0; v < 4; v++) { aR[mt][nt][v] = 0.f; aU[mt][nt][v] = 0.f; }
#pragma unroll
    for (int ktp = 0; ktp < 2; ktp++) {
        uint4 bRx[2], bRs[2], bUx[2], bUs[2];
#pragma unroll
        for (int nt = 0; nt < 2; nt++) {
            int nr = 2 * nq + nt, nu = nr + 8;
            bRx[nt] = *(const uint4*)&gWl[(nr * 2 + ktp) * 128 + lane * 4];
            bRs[nt] = *(const uint4*)&gWl[((16 + nr) * 2 + ktp) * 128 + lane * 4];
            bUx[nt] = *(const uint4*)&gWl[(nu * 2 + ktp) * 128 + lane * 4];
            bUs[nt] = *(const uint4*)&gWl[((16 + nu) * 2 + ktp) * 128 + lane * 4];
        }
#pragma unroll
        for (int k2 = 0; k2 < 2; k2++) {
            int kt = 2 * ktp + k2;
            uint4 ax[2], as2[2];
#pragma unroll
            for (int mt = 0; mt < 2; mt++) {
                int toff = ((2 * mp + mt) * 4 + kt) * 128 + lane * 4;
                ax[mt] = *(const uint4*)&Xc[toff];
                as2[mt] = *(const uint4*)&Sf[toff];
            }
#pragma unroll
            for (int nt = 0; nt < 2; nt++) {
                uint32 rx0 = k2 ? bRx[nt].z : bRx[nt].x, rx1 = k2 ? bRx[nt].w : bRx[nt].y;
                uint32 rs0 = k2 ? bRs[nt].z : bRs[nt].x, rs1 = k2 ? bRs[nt].w : bRs[nt].y;
                uint32 ux0 = k2 ? bUx[nt].z : bUx[nt].x, ux1 = k2 ? bUx[nt].w : bUx[nt].y;
                uint32 us0 = k2 ? bUs[nt].z : bUs[nt].x, us1 = k2 ? bUs[nt].w : bUs[nt].y;
#pragma unroll
                for (int mt = 0; mt < 2; mt++) {
                    mma_f16(aR[mt][nt], ax[mt], rx0, rx1);
                    mma_f16(aR[mt][nt], as2[mt], rs0, rs1);
                    mma_f16(aU[mt][nt], ax[mt], ux0, ux1);
                    mma_f16(aU[mt][nt], as2[mt], us0, us1);
                }
            }
        }
    }
    // ---- epilogue A: sigmoids; r*s -> Rf frags; u in regs ----
    float uv[2][2][4];
#pragma unroll
    for (int mt = 0; mt < 2; mt++) {
        uint32 o[4];
#pragma unroll
        for (int nt = 0; nt < 2; nt++) {
            float r0 = sigm_a(aR[mt][nt][0] + bgr[nt][0]);
            float r1 = sigm_a(aR[mt][nt][1] + bgr[nt][1]);
            float r2 = sigm_a(aR[mt][nt][2] + bgr[nt][0]);
            float r3 = sigm_a(aR[mt][nt][3] + bgr[nt][1]);
            uv[mt][nt][0] = sigm_a(aU[mt][nt][0] + bgu[nt][0]);
            uv[mt][nt][1] = sigm_a(aU[mt][nt][1] + bgu[nt][1]);
            uv[mt][nt][2] = sigm_a(aU[mt][nt][2] + bgu[nt][0]);
            uv[mt][nt][3] = sigm_a(aU[mt][nt][3] + bgu[nt][1]);
            o[2 * nt + 0] = packh2(r0 * sr[mt][nt][0], r1 * sr[mt][nt][1]);
            o[2 * nt + 1] = packh2(r2 * sr[mt][nt][2], r3 * sr[mt][nt][3]);
        }
        *(uint4*)&Rf[((2 * mp + mt) * 4 + nq) * 128 + (4 * g + tig) * 4] =
            make_uint4(o[0], o[1], o[2], o[3]);
    }
    if (inst) {
        ((uint4*)Xn)[tid] = pf0;
        ((uint4*)Xn)[tid + 256] = pf1;
    }
    __syncthreads();
    // ---- phase B: candidate ----
    float aC[2][2][4];
#pragma unroll
    for (int mt = 0; mt < 2; mt++)
#pragma unroll
        for (int nt = 0; nt < 2; nt++)
#pragma unroll
            for (int v = 0; v < 4; v++) aC[mt][nt][v] = 0.f;
#pragma unroll
    for (int ktp = 0; ktp < 2; ktp++) {
        uint4 bCx[2], bCs[2];
#pragma unroll
        for (int nt = 0; nt < 2; nt++) {
            int nc = 2 * nq + nt;
            bCx[nt] = *(const uint4*)&cWl[(nc * 2 + ktp) * 128 + lane * 4];
            bCs[nt] = *(const uint4*)&cWl[((8 + nc) * 2 + ktp) * 128 + lane * 4];
        }
#pragma unroll
        for (int k2 = 0; k2 < 2; k2++) {
            int kt = 2 * ktp + k2;
            uint4 ax[2], ar[2];
#pragma unroll
            for (int mt = 0; mt < 2; mt++) {
                int toff = ((2 * mp + mt) * 4 + kt) * 128 + lane * 4;
                ax[mt] = *(const uint4*)&Xc[toff];
                ar[mt] = *(const uint4*)&Rf[toff];
            }
#pragma unroll
            for (int nt = 0; nt < 2; nt++) {
                uint32 x0 = k2 ? bCx[nt].z : bCx[nt].x, x1 = k2 ? bCx[nt].w : bCx[nt].y;
                uint32 s0 = k2 ? bCs[nt].z : bCs[nt].x, s1 = k2 ? bCs[nt].w : bCs[nt].y;
#pragma unroll
                for (int mt = 0; mt < 2; mt++) {
                    mma_f16(aC[mt][nt], ax[mt], x0, x1);
                    mma_f16(aC[mt][nt], ar[mt], s0, s1);
                }
            }
        }
    }
    // ---- epilogue B: c = tanh; new = u*s + (1-u)*c; update regs + Sf frags ----
#pragma unroll
    for (int mt = 0; mt < 2; mt++) {
        uint32 o[4];
#pragma unroll
        for (int nt = 0; nt < 2; nt++) {
            float c0 = tanh_fast(aC[mt][nt][0] + bcc[nt][0]);
            float c1 = tanh_fast(aC[mt][nt][1] + bcc[nt][1]);
            float c2 = tanh_fast(aC[mt][nt][2] + bcc[nt][0]);
            float c3 = tanh_fast(aC[mt][nt][3] + bcc[nt][1]);
            float n0 = fmaf(uv[mt][nt][0], sr[mt][nt][0] - c0, c0);
            float n1 = fmaf(uv[mt][nt][1], sr[mt][nt][1] - c1, c1);
            float n2 = fmaf(uv[mt][nt][2], sr[mt][nt][2] - c2, c2);
            float n3 = fmaf(uv[mt][nt][3], sr[mt][nt][3] - c3, c3);
            sr[mt][nt][0] = n0; sr[mt][nt][1] = n1;
            sr[mt][nt][2] = n2; sr[mt][nt][3] = n3;
            o[2 * nt + 0] = packh2(n0, n1);
            o[2 * nt + 1] = packh2(n2, n3);
        }
        *(uint4*)&Sf[((2 * mp + mt) * 4 + nq) * 128 + (4 * g + tig) * 4] =
            make_uint4(o[0], o[1], o[2], o[3]);
    }
    __syncthreads();
}

// ---------------- fused 2-layer DCGRU scan ----------------
// smem (uint32): gW0 8192 | gW1 8192 | cW0 4096 | cW1 4096 | Xf 2*2048 | S1f 2048 | S2f 2048 | Rf 2048 | biases 384 floats
__global__ __launch_bounds__(256, 1) void k_scan(
        const float* __restrict__ bg1_, const float* __restrict__ bc1_,
        const float* __restrict__ bg2_, const float* __restrict__ bc2_) {
    extern __shared__ uint32 smu[];
    uint32* gW0 = smu;
    uint32* gW1 = smu + 8192;
    uint32* cW0 = smu + 16384;
    uint32* cW1 = smu + 20480;
    uint32* Xf  = smu + 24576;
    uint32* S1f = smu + 28672;
    uint32* S2f = smu + 30720;
    uint32* Rf  = smu + 32768;
    float*  sb  = (float*)(smu + 34816);

    int tid = threadIdx.x;
    {
        const uint4* s0 = (const uint4*)g_gWh[0];
        const uint4* s1 = (const uint4*)g_gWh[1];
        uint4* d0 = (uint4*)gW0; uint4* d1 = (uint4*)gW1;
        for (int i = tid; i < 2048; i += 256) { d0[i] = s0[i]; d1[i] = s1[i]; }
        const uint4* c0 = (const uint4*)g_cWh[0];
        const uint4* c1 = (const uint4*)g_cWh[1];
        uint4* e0 = (uint4*)cW0; uint4* e1 = (uint4*)cW1;
        for (int i = tid; i < 1024; i += 256) { e0[i] = c0[i]; e1[i] = c1[i]; }
    }
    if (tid < 128) { sb[tid] = bg1_[tid]; sb[128 + tid] = bg2_[tid]; }
    if (tid < 64)  { sb[256 + tid] = bc1_[tid]; sb[320 + tid] = bc2_[tid]; }
    {
        uint4 z = make_uint4(0, 0, 0, 0);
        uint4* z1 = (uint4*)S1f; uint4* z2 = (uint4*)S2f;
        for (int i = tid; i < 512; i += 256) { z1[i] = z; z2[i] = z; }
    }
    int row0 = blockIdx.x * 64;
    int b = row0 >> 10, ntb = (row0 >> 6) & 15;
    {
        const uint4* s = (const uint4*)&g_XeH[(size_t)(b * Pk * 16 + ntb) * 2048];
        uint4* d = (uint4*)Xf;
        d[tid] = s[tid];
        d[tid + 256] = s[tid + 256];
    }
    __syncthreads();

    int lane = tid & 31, w = tid >> 5;
    int mp = w & 1, nq = w >> 1, g = lane >> 2, tig = lane & 3;

    float bgr1[2][2], bgu1[2][2], bcc1[2][2];
    float bgr2[2][2], bgu2[2][2], bcc2[2][2];
#pragma unroll
    for (int nt = 0; nt < 2; nt++) {
        int j = 16 * nq + 8 * nt + 2 * tig;
        bgr1[nt][0] = sb[j];           bgr1[nt][1] = sb[j + 1];
        bgu1[nt][0] = sb[64 + j];      bgu1[nt][1] = sb[64 + j + 1];
        bgr2[nt][0] = sb[128 + j];     bgr2[nt][1] = sb[128 + j + 1];
        bgu2[nt][0] = sb[192 + j];     bgu2[nt][1] = sb[192 + j + 1];
        bcc1[nt][0] = sb[256 + j];     bcc1[nt][1] = sb[256 + j + 1];
        bcc2[nt][0] = sb[320 + j];     bcc2[nt][1] = sb[320 + j + 1];
    }
    float s1r[2][2][4], s2r[2][2][4];
#pragma unroll
    for (int mt = 0; mt < 2; mt++)
#pragma unroll
        for (int nt = 0; nt < 2; nt++)
#pragma unroll
            for (int v = 0; v < 4; v++) { s1r[mt][nt][v] = 0.f; s2r[mt][nt][v] = 0.f; }

    for (int t = 0; t < Pk; t++) {
        int cur = t & 1;
        uint32* Xc = Xf + cur * 2048;
        uint32* Xn = Xf + (cur ^ 1) * 2048;
        uint4 pf0 = make_uint4(0, 0, 0, 0), pf1 = make_uint4(0, 0, 0, 0);
        bool inst = (t + 1 < Pk);
        if (inst) {
            const uint4* s = (const uint4*)&g_XeH[(size_t)((b * Pk + t + 1) * 16 + ntb) * 2048];
            pf0 = s[tid];
            pf1 = s[tid + 256];
        }
        gru_cell(Xc, S1f, Rf, gW0, cW0, s1r, bgr1, bgu1, bcc1,
                 lane, mp, nq, g, tig, inst, Xn, pf0, pf1, tid);
        gru_cell(S1f, S2f, Rf, gW1, cW1, s2r, bgr2, bgu2, bcc2,
                 lane, mp, nq, g, tig, false, Xn, pf0, pf1, tid);
    }
    // write final layer-2 state
#pragma unroll
    for (int mt = 0; mt < 2; mt++) {
#pragma unroll
        for (int nt = 0; nt < 2; nt++) {
            int j = 16 * nq + 8 * nt + 2 * tig;
            int r0g = row0 + (2 * mp + mt) * 16 + g;
            *(float2*)&g_s2[(size_t)r0g * 64 + j]       = make_float2(s2r[mt][nt][0], s2r[mt][nt][1]);
            *(float2*)&g_s2[(size_t)(r0g + 8) * 64 + j] = make_float2(s2r[mt][nt][2], s2r[mt][nt][3]);
        }
    }
}

// ---------------- FC_out ----------------
__global__ __launch_bounds__(256) void k_fc_out(
        const float* __restrict__ W1, const float* __restrict__ b1,
        const float* __restrict__ W2, const float* __restrict__ b2,
        float* __restrict__ out) {
    __shared__ float sW1[64 * 64];
    __shared__ float sHin[64 * 64];
    __shared__ float sH[64 * 65];
    __shared__ float sW2[64 * 12];
    __shared__ float sb1v[64], sb2v[12];
    int tid = threadIdx.x;
    for (int i = tid; i < 4096; i += 256) sW1[i] = W1[i];
    for (int i = tid; i < 768; i += 256) sW2[i] = W2[i];
    if (tid < 64) sb1v[tid] = b1[tid];
    if (tid < 12) sb2v[tid] = b2[tid];
    int row0 = blockIdx.x * 64;
    for (int i4 = tid; i4 < 1024; i4 += 256) {
        int i = i4 >> 4, c = (i4 & 15) << 2;
        *(float4*)&sHin[i * 64 + c] = *(const float4*)&g_s2[(size_t)(row0 + i) * 64 + c];
    }
    __syncthreads();
    int lane = tid & 31, w = tid >> 5, c0 = lane * 2;
    float acc[8][2];
#pragma unroll
    for (int ri = 0; ri < 8; ri++) { acc[ri][0] = 0.f; acc[ri][1] = 0.f; }
#pragma unroll 8
    for (int k = 0; k < 64; k++) {
        float2 wv = *(const float2*)&sW1[k * 64 + c0];
#pragma unroll
        for (int ri = 0; ri < 8; ri++) {
            float h = sHin[(w + ri * 8) * 64 + k];
            acc[ri][0] = fmaf(h, wv.x, acc[ri][0]);
            acc[ri][1] = fmaf(h, wv.y, acc[ri][1]);
        }
    }
#pragma unroll
    for (int ri = 0; ri < 8; ri++) {
        int i = w + ri * 8;
        sH[i * 65 + c0]     = fmaxf(acc[ri][0] + sb1v[c0], 0.f);
        sH[i * 65 + c0 + 1] = fmaxf(acc[ri][1] + sb1v[c0 + 1], 0.f);
    }
    __syncthreads();
    int i = tid >> 2;
    int q0 = (tid & 3) * 3;
    float a0 = sb2v[q0], a1 = sb2v[q0 + 1], a2 = sb2v[q0 + 2];
#pragma unroll 8
    for (int k = 0; k < 64; k++) {
        float h = sH[i * 65 + k];
        a0 = fmaf(h, sW2[k * 12 + q0],     a0);
        a1 = fmaf(h, sW2[k * 12 + q0 + 1], a1);
        a2 = fmaf(h, sW2[k * 12 + q0 + 2], a2);
    }
    int r = row0 + i, b = r >> 10, n = r & 1023;
    out[(((size_t)b * Qk + q0)     << 10) + n] = a0;
    out[(((size_t)b * Qk + q0 + 1) << 10) + n] = a1;
    out[(((size_t)b * Qk + q0 + 2) << 10) + n] = a2;
}

// ---------------- launch ----------------
extern "C" void kernel_launch(void* const* d_in, const int* in_sizes, int n_in,
                              void* d_out, int out_size) {
    const float* X     = (const float*)d_in[0];
    const float* SE    = (const float*)d_in[3];
    const float* W_se1 = (const float*)d_in[4];  const float* b_se1 = (const float*)d_in[5];
    const float* W_se2 = (const float*)d_in[6];  const float* b_se2 = (const float*)d_in[7];
    const float* W_te1 = (const float*)d_in[8];  const float* b_te1 = (const float*)d_in[9];
    const float* W_te2 = (const float*)d_in[10]; const float* b_te2 = (const float*)d_in[11];
    const float* W_in1 = (const float*)d_in[12]; const float* b_in1 = (const float*)d_in[13];
    const float* W_in2 = (const float*)d_in[14]; const float* b_in2 = (const float*)d_in[15];
    const float* Wg1   = (const float*)d_in[16]; const float* bg1   = (const float*)d_in[17];
    const float* Wc1   = (const float*)d_in[18]; const float* bc1   = (const float*)d_in[19];
    const float* Wg2   = (const float*)d_in[20]; const float* bg2   = (const float*)d_in[21];
    const float* Wc2   = (const float*)d_in[22]; const float* bc2   = (const float*)d_in[23];
    const float* W_o1  = (const float*)d_in[24]; const float* b_o1  = (const float*)d_in[25];
    const float* W_o2  = (const float*)d_in[26]; const float* b_o2  = (const float*)d_in[27];
    const int*   TE    = (const int*)d_in[28];
    float* out = (float*)d_out;

    const size_t scan_smem = (size_t)35200 * 4;   // 140,800 B
    cudaFuncSetAttribute(k_scan, cudaFuncAttributeMaxDynamicSharedMemorySize,
                         (int)scan_smem);

    k_prep<<<64, 256>>>(Wg1, Wc1, Wg2, Wc2);
    k_prep_seg<<<1, 256>>>(W_in1, b_in1, W_in2, b_in2);
    k_se<<<Nk, 64>>>(SE, W_se1, b_se1, W_se2, b_se2);
    k_te<<<Bk * Pk, 64>>>(TE, W_te1, b_te1, W_te2, b_te2);
    k_fc_in_h<<<Bk * Pk, 256>>>(X);

    k_scan<<<Bk * Nk / 64, 256, scan_smem>>>(bg1, bc1, bg2, bc2);

    k_fc_out<<<Bk * Nk / 64, 256>>>(W_o1, b_o1, W_o2, b_o2, out);
}

// round 12
// speedup vs baseline: 7.5907x; 1.0031x over previous
#include <cuda_runtime.h>
#include <cuda_fp16.h>

#define Bk 64
#define Pk 12
#define Qk 12
#define Nk 1024
#define Dk 64

typedef unsigned int uint32;

__device__ __forceinline__ uint32 packh2(float a, float b) {
    __half2 h = __floats2half2_rn(a, b);
    return *(uint32*)&h;
}
__device__ __forceinline__ void mma_f16(float* d, uint4 a, uint32 b0, uint32 b1) {
    asm("mma.sync.aligned.m16n8k16.row.col.f32.f16.f16.f32 "
        "{%0,%1,%2,%3},{%4,%5,%6,%7},{%8,%9},{%0,%1,%2,%3};"
        : "+f"(d[0]), "+f"(d[1]), "+f"(d[2]), "+f"(d[3])
        : "r"(a.x), "r"(a.y), "r"(a.z), "r"(a.w), "r"(b0), "r"(b1));
}
__device__ __forceinline__ float tanh_a(float z) {
    float y;
    asm("tanh.approx.f32 %0, %1;" : "=f"(y) : "f"(z));
    return y;
}
__device__ __forceinline__ float sigm_a(float z) {
    return fmaf(0.5f, tanh_a(0.5f * z), 0.5f);
}
__device__ __forceinline__ float tanh_fast(float z) {
    z = fminf(fmaxf(z, -15.f), 15.f);
    float e = __expf(-2.f * z);
    return __fdividef(1.f - e, 1.f + e);
}

// ---------------- scratch ----------------
__device__ float g_se[Nk * Dk];
__device__ float g_te[Bk * Pk * Dk];
__device__ float g_s2[Bk * Nk * Dk];
__device__ uint32 g_XeH[(size_t)Bk * Pk * 16 * 2048];
__device__ uint32 g_gWh[2][8192];
__device__ uint32 g_cWh[2][4096];
__device__ float g_alpha[65 * 64];
__device__ float g_beta[65 * 64];
__device__ float g_ts[64];

// ---------------- weight folding + fp16 frag packing ----------------
__global__ void k_prep(const float* __restrict__ Wg1, const float* __restrict__ Wc1,
                       const float* __restrict__ Wg2, const float* __restrict__ Wc2) {
    int tid = blockIdx.x * blockDim.x + threadIdx.x;
    int stride = gridDim.x * blockDim.x;
    for (int i = tid; i < 16384; i += stride) {
        int v = i & 3, lane = (i >> 2) & 31, ktp = (i >> 7) & 1;
        int n8 = (i >> 8) & 15, pt = (i >> 12) & 1, l = (i >> 13) & 1;
        int kt = 2 * ktp + (v >> 1), reg = v & 1;
        int g = lane >> 2, tig = lane & 3;
        int k0 = kt * 16 + 2 * tig + 8 * reg;
        int n = n8 * 8 + g;
        const float* W = l ? Wg2 : Wg1;
        int r0 = pt * 64;
        float f0 = W[(r0 + k0) * 128 + n] + W[(r0 + 128 + k0) * 128 + n];
        float f1 = W[(r0 + k0 + 1) * 128 + n] + W[(r0 + 129 + k0) * 128 + n];
        g_gWh[l][((pt * 16 + n8) * 2 + ktp) * 128 + lane * 4 + v] = packh2(f0, f1);
    }
    for (int i = tid; i < 8192; i += stride) {
        int v = i & 3, lane = (i >> 2) & 31, ktp = (i >> 7) & 1;
        int n8 = (i >> 8) & 7, pt = (i >> 11) & 1, l = (i >> 12) & 1;
        int kt = 2 * ktp + (v >> 1), reg = v & 1;
        int g = lane >> 2, tig = lane & 3;
        int k0 = kt * 16 + 2 * tig + 8 * reg;
        int n = n8 * 8 + g;
        const float* W = l ? Wc2 : Wc1;
        int r0 = pt * 64;
        float f0 = W[(r0 + k0) * 64 + n] + W[(r0 + 128 + k0) * 64 + n];
        float f1 = W[(r0 + k0 + 1) * 64 + n] + W[(r0 + 129 + k0) * 64 + n];
        g_cWh[l][((pt * 8 + n8) * 2 + ktp) * 128 + lane * 4 + v] = packh2(f0, f1);
    }
}

// ---------------- fc_in piecewise-linear precompute ----------------
__global__ void k_prep_seg(const float* __restrict__ W1, const float* __restrict__ b1,
                           const float* __restrict__ W2, const float* __restrict__ b2) {
    __shared__ float w1s[64], b1s[64], tsr[64];
    __shared__ int rnk[64];
    int tid = threadIdx.x;
    if (tid < 64) { w1s[tid] = W1[tid]; b1s[tid] = b1[tid]; }
    __syncthreads();
    if (tid < 64) {
        float w = w1s[tid];
        tsr[tid] = (w != 0.f) ? (-b1s[tid] / w) : __int_as_float(0x7f800000);
    }
    __syncthreads();
    if (tid < 64) {
        float t = tsr[tid];
        int r = 0;
        for (int d = 0; d < 64; d++) {
            float td = tsr[d];
            r += (td < t) || (td == t && d < tid);
        }
        rnk[tid] = r;
        g_ts[r] = t;
    }
    __syncthreads();
    for (int idx = tid; idx < 65 * 64; idx += blockDim.x) {
        int s = idx >> 6, c = idx & 63;
        float a = 0.f, bt = 0.f;
        for (int d = 0; d < 64; d++) {
            float w = w1s[d];
            bool act = (w > 0.f) ? (rnk[d] < s)
                     : ((w < 0.f) ? (rnk[d] >= s) : (b1s[d] > 0.f));
            if (act) {
                float w2 = W2[d * 64 + c];
                a = fmaf(w, w2, a);
                bt = fmaf(b1s[d], w2, bt);
            }
        }
        g_alpha[idx] = a;
        g_beta[idx] = bt + b2[c];
    }
}

// ---------------- spatial embedding ----------------
__global__ void k_se(const float* __restrict__ SE, const float* __restrict__ W1,
                     const float* __restrict__ b1, const float* __restrict__ W2,
                     const float* __restrict__ b2) {
    __shared__ float xs[64], hs[64];
    int n = blockIdx.x, d = threadIdx.x;
    xs[d] = SE[n * 64 + d];
    __syncthreads();
    float a = b1[d];
#pragma unroll 8
    for (int k = 0; k < 64; k++) a = fmaf(xs[k], W1[k * 64 + d], a);
    hs[d] = fmaxf(a, 0.f);
    __syncthreads();
    float o = b2[d];
#pragma unroll 8
    for (int k = 0; k < 64; k++) o = fmaf(hs[k], W2[k * 64 + d], o);
    g_se[n * 64 + d] = o;
}

// ---------------- temporal embedding ----------------
__global__ void k_te(const int* __restrict__ TE, const float* __restrict__ W1,
                     const float* __restrict__ b1, const float* __restrict__ W2,
                     const float* __restrict__ b2) {
    __shared__ float hs[64];
    int row = blockIdx.x;
    int b = row / Pk, p = row - b * Pk;
    int d = threadIdx.x;
    int base = (b * (Pk + Qk) + p) * 2;
    int t0 = TE[base], t1 = TE[base + 1];
    float a = W1[t0 * 64 + d] + W1[(7 + t1) * 64 + d] + b1[d];
    hs[d] = fmaxf(a, 0.f);
    __syncthreads();
    float o = b2[d];
#pragma unroll 8
    for (int k = 0; k < 64; k++) o = fmaf(hs[k], W2[k * 64 + d], o);
    g_te[row * 64 + d] = o;
}

// ---------------- FC_in: closed-form affine -> fp16 frag output ----------------
__global__ __launch_bounds__(256) void k_fc_in_h(const float* __restrict__ X) {
    __shared__ float sA[65 * 64], sB[65 * 64], sTs[64], sTe[64];
    __shared__ float sXs[1024];
    __shared__ int sSeg[1024];
    int tid = threadIdx.x;
    int bp = blockIdx.x;
    {
        const float4* a = (const float4*)g_alpha;
        const float4* b = (const float4*)g_beta;
        float4* da = (float4*)sA;
        float4* db = (float4*)sB;
        for (int i = tid; i < 1040; i += 256) { da[i] = a[i]; db[i] = b[i]; }
    }
    if (tid < 64) { sTs[tid] = g_ts[tid]; sTe[tid] = g_te[bp * 64 + tid]; }
    __syncthreads();
    for (int i = tid; i < 1024; i += 256) {
        float x = X[(size_t)bp * 1024 + i];
        sXs[i] = x;
        int sg = 0;
#pragma unroll 16
        for (int k = 0; k < 64; k++) sg += (sTs[k] < x);
        sSeg[i] = sg;
    }
    __syncthreads();
#pragma unroll 4
    for (int it = 0; it < 32; it++) {
        int sl = it * 256 + tid;
        int nt = sl >> 9, r9 = sl & 511;
        int mt = r9 >> 7, kt = (r9 >> 5) & 3, s = r9 & 31;
        int g = s >> 2, tig = s & 3;
        int n0 = nt * 64 + 16 * mt + g, n1 = n0 + 8;
        int c0 = 16 * kt + 2 * tig, c1 = c0 + 8;
        float x0 = sXs[n0], x1 = sXs[n1];
        int s0 = sSeg[n0] * 64, s1 = sSeg[n1] * 64;
        float2 a00 = *(const float2*)&sA[s0 + c0], b00 = *(const float2*)&sB[s0 + c0];
        float2 a01 = *(const float2*)&sA[s0 + c1], b01 = *(const float2*)&sB[s0 + c1];
        float2 a10 = *(const float2*)&sA[s1 + c0], b10 = *(const float2*)&sB[s1 + c0];
        float2 a11 = *(const float2*)&sA[s1 + c1], b11 = *(const float2*)&sB[s1 + c1];
        float2 se00 = *(const float2*)&g_se[n0 * 64 + c0];
        float2 se01 = *(const float2*)&g_se[n0 * 64 + c1];
        float2 se10 = *(const float2*)&g_se[n1 * 64 + c0];
        float2 se11 = *(const float2*)&g_se[n1 * 64 + c1];
        float2 te0 = *(const float2*)&sTe[c0];
        float2 te1 = *(const float2*)&sTe[c1];
        uint32 u0 = packh2(fmaf(x0, a00.x, b00.x) + se00.x + te0.x,
                           fmaf(x0, a00.y, b00.y) + se00.y + te0.y);
        uint32 u1 = packh2(fmaf(x1, a10.x, b10.x) + se10.x + te0.x,
                           fmaf(x1, a10.y, b10.y) + se10.y + te0.y);
        uint32 u2 = packh2(fmaf(x0, a01.x, b01.x) + se01.x + te1.x,
                           fmaf(x0, a01.y, b01.y) + se01.y + te1.y);
        uint32 u3 = packh2(fmaf(x1, a11.x, b11.x) + se11.x + te1.x,
                           fmaf(x1, a11.y, b11.y) + se11.y + te1.y);
        *(uint4*)&g_XeH[(size_t)(bp * 16 + nt) * 2048 + (mt * 4 + kt) * 128 + s * 4] =
            make_uint4(u0, u1, u2, u3);
    }
}

// ---------------- GRU phase helpers (fp16 frags) ----------------
__device__ __forceinline__ void phaseA(
        const uint32* __restrict__ Xc, const uint32* __restrict__ Sf,
        const uint32* __restrict__ gWl,
        float (&aR)[2][2][4], float (&aU)[2][2][4], int lane, int mp, int nq) {
#pragma unroll
    for (int mt = 0; mt < 2; mt++)
#pragma unroll
        for (int nt = 0; nt < 2; nt++)
#pragma unroll
            for (int v = 0; v < 4; v++) { aR[mt][nt][v] = 0.f; aU[mt][nt][v] = 0.f; }
#pragma unroll
    for (int ktp = 0; ktp < 2; ktp++) {
        uint4 bRx[2], bRs[2], bUx[2], bUs[2];
#pragma unroll
        for (int nt = 0; nt < 2; nt++) {
            int nr = 2 * nq + nt, nu = nr + 8;
            bRx[nt] = *(const uint4*)&gWl[(nr * 2 + ktp) * 128 + lane * 4];
            bRs[nt] = *(const uint4*)&gWl[((16 + nr) * 2 + ktp) * 128 + lane * 4];
            bUx[nt] = *(const uint4*)&gWl[(nu * 2 + ktp) * 128 + lane * 4];
            bUs[nt] = *(const uint4*)&gWl[((16 + nu) * 2 + ktp) * 128 + lane * 4];
        }
#pragma unroll
        for (int k2 = 0; k2 < 2; k2++) {
            int kt = 2 * ktp + k2;
            uint4 ax[2], as2[2];
#pragma unroll
            for (int mt = 0; mt < 2; mt++) {
                int toff = ((2 * mp + mt) * 4 + kt) * 128 + lane * 4;
                ax[mt] = *(const uint4*)&Xc[toff];
                as2[mt] = *(const uint4*)&Sf[toff];
            }
#pragma unroll
            for (int nt = 0; nt < 2; nt++) {
                uint32 rx0 = k2 ? bRx[nt].z : bRx[nt].x, rx1 = k2 ? bRx[nt].w : bRx[nt].y;
                uint32 rs0 = k2 ? bRs[nt].z : bRs[nt].x, rs1 = k2 ? bRs[nt].w : bRs[nt].y;
                uint32 ux0 = k2 ? bUx[nt].z : bUx[nt].x, ux1 = k2 ? bUx[nt].w : bUx[nt].y;
                uint32 us0 = k2 ? bUs[nt].z : bUs[nt].x, us1 = k2 ? bUs[nt].w : bUs[nt].y;
#pragma unroll
                for (int mt = 0; mt < 2; mt++) {
                    mma_f16(aR[mt][nt], ax[mt], rx0, rx1);
                    mma_f16(aR[mt][nt], as2[mt], rs0, rs1);
                    mma_f16(aU[mt][nt], ax[mt], ux0, ux1);
                    mma_f16(aU[mt][nt], as2[mt], us0, us1);
                }
            }
        }
    }
}

__device__ __forceinline__ void epiA(
        const float (&aR)[2][2][4], const float (&aU)[2][2][4],
        const float (&bgr)[2][2], const float (&bgu)[2][2],
        const float (&sr)[2][2][4], float (&uv)[2][2][4],
        uint32* __restrict__ Rf, int mp, int nq, int g, int tig) {
#pragma unroll
    for (int mt = 0; mt < 2; mt++) {
        uint32 o[4];
#pragma unroll
        for (int nt = 0; nt < 2; nt++) {
            float r0 = sigm_a(aR[mt][nt][0] + bgr[nt][0]);
            float r1 = sigm_a(aR[mt][nt][1] + bgr[nt][1]);
            float r2 = sigm_a(aR[mt][nt][2] + bgr[nt][0]);
            float r3 = sigm_a(aR[mt][nt][3] + bgr[nt][1]);
            uv[mt][nt][0] = sigm_a(aU[mt][nt][0] + bgu[nt][0]);
            uv[mt][nt][1] = sigm_a(aU[mt][nt][1] + bgu[nt][1]);
            uv[mt][nt][2] = sigm_a(aU[mt][nt][2] + bgu[nt][0]);
            uv[mt][nt][3] = sigm_a(aU[mt][nt][3] + bgu[nt][1]);
            o[2 * nt + 0] = packh2(r0 * sr[mt][nt][0], r1 * sr[mt][nt][1]);
            o[2 * nt + 1] = packh2(r2 * sr[mt][nt][2], r3 * sr[mt][nt][3]);
        }
        *(uint4*)&Rf[((2 * mp + mt) * 4 + nq) * 128 + (4 * g + tig) * 4] =
            make_uint4(o[0], o[1], o[2], o[3]);
    }
}

__device__ __forceinline__ void phaseB(
        const uint32* __restrict__ Xc, const uint32* __restrict__ Rf,
        const uint32* __restrict__ cWl, float (&aC)[2][2][4], int lane, int mp, int nq) {
#pragma unroll
    for (int mt = 0; mt < 2; mt++)
#pragma unroll
        for (int nt = 0; nt < 2; nt++)
#pragma unroll
            for (int v = 0; v < 4; v++) aC[mt][nt][v] = 0.f;
#pragma unroll
    for (int ktp = 0; ktp < 2; ktp++) {
        uint4 bCx[2], bCs[2];
#pragma unroll
        for (int nt = 0; nt < 2; nt++) {
            int nc = 2 * nq + nt;
            bCx[nt] = *(const uint4*)&cWl[(nc * 2 + ktp) * 128 + lane * 4];
            bCs[nt] = *(const uint4*)&cWl[((8 + nc) * 2 + ktp) * 128 + lane * 4];
        }
#pragma unroll
        for (int k2 = 0; k2 < 2; k2++) {
            int kt = 2 * ktp + k2;
            uint4 ax[2], ar[2];
#pragma unroll
            for (int mt = 0; mt < 2; mt++) {
                int toff = ((2 * mp + mt) * 4 + kt) * 128 + lane * 4;
                ax[mt] = *(const uint4*)&Xc[toff];
                ar[mt] = *(const uint4*)&Rf[toff];
            }
#pragma unroll
            for (int nt = 0; nt < 2; nt++) {
                uint32 x0 = k2 ? bCx[nt].z : bCx[nt].x, x1 = k2 ? bCx[nt].w : bCx[nt].y;
                uint32 s0 = k2 ? bCs[nt].z : bCs[nt].x, s1 = k2 ? bCs[nt].w : bCs[nt].y;
#pragma unroll
                for (int mt = 0; mt < 2; mt++) {
                    mma_f16(aC[mt][nt], ax[mt], x0, x1);
                    mma_f16(aC[mt][nt], ar[mt], s0, s1);
                }
            }
        }
    }
}

__device__ __forceinline__ void epiB(
        const float (&aC)[2][2][4], const float (&bcc)[2][2],
        const float (&uv)[2][2][4], float (&sr)[2][2][4],
        uint32* __restrict__ Sf, int mp, int nq, int g, int tig) {
#pragma unroll
    for (int mt = 0; mt < 2; mt++) {
        uint32 o[4];
#pragma unroll
        for (int nt = 0; nt < 2; nt++) {
            float c0 = tanh_fast(aC[mt][nt][0] + bcc[nt][0]);
            float c1 = tanh_fast(aC[mt][nt][1] + bcc[nt][1]);
            float c2 = tanh_fast(aC[mt][nt][2] + bcc[nt][0]);
            float c3 = tanh_fast(aC[mt][nt][3] + bcc[nt][1]);
            float n0 = fmaf(uv[mt][nt][0], sr[mt][nt][0] - c0, c0);
            float n1 = fmaf(uv[mt][nt][1], sr[mt][nt][1] - c1, c1);
            float n2 = fmaf(uv[mt][nt][2], sr[mt][nt][2] - c2, c2);
            float n3 = fmaf(uv[mt][nt][3], sr[mt][nt][3] - c3, c3);
            sr[mt][nt][0] = n0; sr[mt][nt][1] = n1;
            sr[mt][nt][2] = n2; sr[mt][nt][3] = n3;
            o[2 * nt + 0] = packh2(n0, n1);
            o[2 * nt + 1] = packh2(n2, n3);
        }
        *(uint4*)&Sf[((2 * mp + mt) * 4 + nq) * 128 + (4 * g + tig) * 4] =
            make_uint4(o[0], o[1], o[2], o[3]);
    }
}

// ---------------- fused 2-layer DCGRU scan, cross-layer software pipeline ----------------
// smem (uint32): gW0 8192 | gW1 8192 | cW0 4096 | cW1 4096 | Xf 2x2048 | S1f 2x2048 |
//                S2f 2048 | Rf1 2048 | Rf2 2048 | biases 384 floats   -> 39296 u32
__global__ __launch_bounds__(256, 1) void k_scan(
        const float* __restrict__ bg1_, const float* __restrict__ bc1_,
        const float* __restrict__ bg2_, const float* __restrict__ bc2_) {
    extern __shared__ uint32 smu[];
    uint32* gW0 = smu;
    uint32* gW1 = smu + 8192;
    uint32* cW0 = smu + 16384;
    uint32* cW1 = smu + 20480;
    uint32* Xf  = smu + 24576;
    uint32* S1f = smu + 28672;
    uint32* S2f = smu + 32768;
    uint32* Rf1 = smu + 34816;
    uint32* Rf2 = smu + 36864;
    float*  sb  = (float*)(smu + 38912);

    int tid = threadIdx.x;
    {
        const uint4* s0 = (const uint4*)g_gWh[0];
        const uint4* s1 = (const uint4*)g_gWh[1];
        uint4* d0 = (uint4*)gW0; uint4* d1 = (uint4*)gW1;
        for (int i = tid; i < 2048; i += 256) { d0[i] = s0[i]; d1[i] = s1[i]; }
        const uint4* c0 = (const uint4*)g_cWh[0];
        const uint4* c1 = (const uint4*)g_cWh[1];
        uint4* e0 = (uint4*)cW0; uint4* e1 = (uint4*)cW1;
        for (int i = tid; i < 1024; i += 256) { e0[i] = c0[i]; e1[i] = c1[i]; }
    }
    if (tid < 128) { sb[tid] = bg1_[tid]; sb[128 + tid] = bg2_[tid]; }
    if (tid < 64)  { sb[256 + tid] = bc1_[tid]; sb[320 + tid] = bc2_[tid]; }
    {
        uint4 z = make_uint4(0, 0, 0, 0);
        uint4* z1 = (uint4*)S1f; uint4* z2 = (uint4*)S2f;
        for (int i = tid; i < 1024; i += 256) z1[i] = z;   // both S1f buffers
        for (int i = tid; i < 512; i += 256) z2[i] = z;
    }
    int row0 = blockIdx.x * 64;
    int b = row0 >> 10, ntb = (row0 >> 6) & 15;
    {   // x(0) -> Xf[0], x(1) -> Xf[1]
        const uint4* s0 = (const uint4*)&g_XeH[(size_t)(b * Pk * 16 + ntb) * 2048];
        const uint4* s1 = (const uint4*)&g_XeH[(size_t)((b * Pk + 1) * 16 + ntb) * 2048];
        uint4* d0 = (uint4*)Xf;
        uint4* d1 = (uint4*)(Xf + 2048);
        d0[tid] = s0[tid]; d0[tid + 256] = s0[tid + 256];
        d1[tid] = s1[tid]; d1[tid + 256] = s1[tid + 256];
    }
    __syncthreads();

    int lane = tid & 31, w = tid >> 5;
    int mp = w & 1, nq = w >> 1, g = lane >> 2, tig = lane & 3;

    float bgr1[2][2], bgu1[2][2], bcc1[2][2];
    float bgr2[2][2], bgu2[2][2], bcc2[2][2];
#pragma unroll
    for (int nt = 0; nt < 2; nt++) {
        int j = 16 * nq + 8 * nt + 2 * tig;
        bgr1[nt][0] = sb[j];           bgr1[nt][1] = sb[j + 1];
        bgu1[nt][0] = sb[64 + j];      bgu1[nt][1] = sb[64 + j + 1];
        bgr2[nt][0] = sb[128 + j];     bgr2[nt][1] = sb[128 + j + 1];
        bgu2[nt][0] = sb[192 + j];     bgu2[nt][1] = sb[192 + j + 1];
        bcc1[nt][0] = sb[256 + j];     bcc1[nt][1] = sb[256 + j + 1];
        bcc2[nt][0] = sb[320 + j];     bcc2[nt][1] = sb[320 + j + 1];
    }
    float s1r[2][2][4], s2r[2][2][4];
#pragma unroll
    for (int mt = 0; mt < 2; mt++)
#pragma unroll
        for (int nt = 0; nt < 2; nt++)
#pragma unroll
            for (int v = 0; v < 4; v++) { s1r[mt][nt][v] = 0.f; s2r[mt][nt][v] = 0.f; }

    float aR1[2][2][4], aU1[2][2][4], aR2[2][2][4], aU2[2][2][4];
    float uv1[2][2][4], uv2[2][2][4];
    float aC1[2][2][4], aC2[2][2][4];

    // ---- standalone L1 at t=0: x in Xf[0], state zeros in S1f[1], writes S1f[0] ----
    phaseA(Xf, S1f + 2048, gW0, aR1, aU1, lane, mp, nq);
    epiA(aR1, aU1, bgr1, bgu1, s1r, uv1, Rf1, mp, nq, g, tig);
    __syncthreads();
    phaseB(Xf, Rf1, cW0, aC1, lane, mp, nq);
    epiB(aC1, bcc1, uv1, s1r, S1f, mp, nq, g, tig);
    __syncthreads();

    // ---- fused supersteps: L1 at t=k+1 with L2 at t=k ----
    for (int k = 0; k <= 10; k++) {
        int p = k & 1;
        uint32* Xc  = Xf + ((k + 1) & 1) * 2048;
        uint32* S1c = S1f + p * 2048;
        uint32* S1n = S1f + (p ^ 1) * 2048;
        uint4 pf0 = make_uint4(0, 0, 0, 0), pf1 = make_uint4(0, 0, 0, 0);
        bool inst = (k + 2 < Pk);
        if (inst) {
            const uint4* s = (const uint4*)&g_XeH[(size_t)((b * Pk + k + 2) * 16 + ntb) * 2048];
            pf0 = s[tid];
            pf1 = s[tid + 256];
        }
        phaseA(Xc, S1c, gW0, aR1, aU1, lane, mp, nq);
        phaseA(S1c, S2f, gW1, aR2, aU2, lane, mp, nq);
        epiA(aR1, aU1, bgr1, bgu1, s1r, uv1, Rf1, mp, nq, g, tig);
        epiA(aR2, aU2, bgr2, bgu2, s2r, uv2, Rf2, mp, nq, g, tig);
        if (inst) {
            uint4* d = (uint4*)(Xf + (k & 1) * 2048);
            d[tid] = pf0;
            d[tid + 256] = pf1;
        }
        __syncthreads();
        phaseB(Xc, Rf1, cW0, aC1, lane, mp, nq);
        phaseB(S1c, Rf2, cW1, aC2, lane, mp, nq);
        epiB(aC1, bcc1, uv1, s1r, S1n, mp, nq, g, tig);
        epiB(aC2, bcc2, uv2, s2r, S2f, mp, nq, g, tig);
        __syncthreads();
    }

    // ---- standalone L2 at t=11: input S1(11) in S1f[1] ----
    phaseA(S1f + 2048, S2f, gW1, aR2, aU2, lane, mp, nq);
    epiA(aR2, aU2, bgr2, bgu2, s2r, uv2, Rf2, mp, nq, g, tig);
    __syncthreads();
    phaseB(S1f + 2048, Rf2, cW1, aC2, lane, mp, nq);
    epiB(aC2, bcc2, uv2, s2r, S2f, mp, nq, g, tig);

    // write final layer-2 state
#pragma unroll
    for (int mt = 0; mt < 2; mt++) {
#pragma unroll
        for (int nt = 0; nt < 2; nt++) {
            int j = 16 * nq + 8 * nt + 2 * tig;
            int r0g = row0 + (2 * mp + mt) * 16 + g;
            *(float2*)&g_s2[(size_t)r0g * 64 + j]       = make_float2(s2r[mt][nt][0], s2r[mt][nt][1]);
            *(float2*)&g_s2[(size_t)(r0g + 8) * 64 + j] = make_float2(s2r[mt][nt][2], s2r[mt][nt][3]);
        }
    }
}

// ---------------- FC_out ----------------
__global__ __launch_bounds__(256) void k_fc_out(
        const float* __restrict__ W1, const float* __restrict__ b1,
        const float* __restrict__ W2, const float* __restrict__ b2,
        float* __restrict__ out) {
    __shared__ float sW1[64 * 64];
    __shared__ float sHin[64 * 64];
    __shared__ float sH[64 * 65];
    __shared__ float sW2[64 * 12];
    __shared__ float sb1v[64], sb2v[12];
    int tid = threadIdx.x;
    for (int i = tid; i < 4096; i += 256) sW1[i] = W1[i];
    for (int i = tid; i < 768; i += 256) sW2[i] = W2[i];
    if (tid < 64) sb1v[tid] = b1[tid];
    if (tid < 12) sb2v[tid] = b2[tid];
    int row0 = blockIdx.x * 64;
    for (int i4 = tid; i4 < 1024; i4 += 256) {
        int i = i4 >> 4, c = (i4 & 15) << 2;
        *(float4*)&sHin[i * 64 + c] = *(const float4*)&g_s2[(size_t)(row0 + i) * 64 + c];
    }
    __syncthreads();
    int lane = tid & 31, w = tid >> 5, c0 = lane * 2;
    float acc[8][2];
#pragma unroll
    for (int ri = 0; ri < 8; ri++) { acc[ri][0] = 0.f; acc[ri][1] = 0.f; }
#pragma unroll 8
    for (int k = 0; k < 64; k++) {
        float2 wv = *(const float2*)&sW1[k * 64 + c0];
#pragma unroll
        for (int ri = 0; ri < 8; ri++) {
            float h = sHin[(w + ri * 8) * 64 + k];
            acc[ri][0] = fmaf(h, wv.x, acc[ri][0]);
            acc[ri][1] = fmaf(h, wv.y, acc[ri][1]);
        }
    }
#pragma unroll
    for (int ri = 0; ri < 8; ri++) {
        int i = w + ri * 8;
        sH[i * 65 + c0]     = fmaxf(acc[ri][0] + sb1v[c0], 0.f);
        sH[i * 65 + c0 + 1] = fmaxf(acc[ri][1] + sb1v[c0 + 1], 0.f);
    }
    __syncthreads();
    int i = tid >> 2;
    int q0 = (tid & 3) * 3;
    float a0 = sb2v[q0], a1 = sb2v[q0 + 1], a2 = sb2v[q0 + 2];
#pragma unroll 8
    for (int k = 0; k < 64; k++) {
        float h = sH[i * 65 + k];
        a0 = fmaf(h, sW2[k * 12 + q0],     a0);
        a1 = fmaf(h, sW2[k * 12 + q0 + 1], a1);
        a2 = fmaf(h, sW2[k * 12 + q0 + 2], a2);
    }
    int r = row0 + i, b = r >> 10, n = r & 1023;
    out[(((size_t)b * Qk + q0)     << 10) + n] = a0;
    out[(((size_t)b * Qk + q0 + 1) << 10) + n] = a1;
    out[(((size_t)b * Qk + q0 + 2) << 10) + n] = a2;
}

// ---------------- launch ----------------
extern "C" void kernel_launch(void* const* d_in, const int* in_sizes, int n_in,
                              void* d_out, int out_size) {
    const float* X     = (const float*)d_in[0];
    const float* SE    = (const float*)d_in[3];
    const float* W_se1 = (const float*)d_in[4];  const float* b_se1 = (const float*)d_in[5];
    const float* W_se2 = (const float*)d_in[6];  const float* b_se2 = (const float*)d_in[7];
    const float* W_te1 = (const float*)d_in[8];  const float* b_te1 = (const float*)d_in[9];
    const float* W_te2 = (const float*)d_in[10]; const float* b_te2 = (const float*)d_in[11];
    const float* W_in1 = (const float*)d_in[12]; const float* b_in1 = (const float*)d_in[13];
    const float* W_in2 = (const float*)d_in[14]; const float* b_in2 = (const float*)d_in[15];
    const float* Wg1   = (const float*)d_in[16]; const float* bg1   = (const float*)d_in[17];
    const float* Wc1   = (const float*)d_in[18]; const float* bc1   = (const float*)d_in[19];
    const float* Wg2   = (const float*)d_in[20]; const float* bg2   = (const float*)d_in[21];
    const float* Wc2   = (const float*)d_in[22]; const float* bc2   = (const float*)d_in[23];
    const float* W_o1  = (const float*)d_in[24]; const float* b_o1  = (const float*)d_in[25];
    const float* W_o2  = (const float*)d_in[26]; const float* b_o2  = (const float*)d_in[27];
    const int*   TE    = (const int*)d_in[28];
    float* out = (float*)d_out;

    const size_t scan_smem = (size_t)39296 * 4;   // 157,184 B
    cudaFuncSetAttribute(k_scan, cudaFuncAttributeMaxDynamicSharedMemorySize,
                         (int)scan_smem);

    k_prep<<<64, 256>>>(Wg1, Wc1, Wg2, Wc2);
    k_prep_seg<<<1, 256>>>(W_in1, b_in1, W_in2, b_in2);
    k_se<<<Nk, 64>>>(SE, W_se1, b_se1, W_se2, b_se2);
    k_te<<<Bk * Pk, 64>>>(TE, W_te1, b_te1, W_te2, b_te2);
    k_fc_in_h<<<Bk * Pk, 256>>>(X);

    k_scan<<<Bk * Nk / 64, 256, scan_smem>>>(bg1, bc1, bg2, bc2);

    k_fc_out<<<Bk * Nk / 64, 256>>>(W_o1, b_o1, W_o2, b_o2, out);
}